// round 1
// baseline (speedup 1.0000x reference)
#include <cuda_runtime.h>
#include <math.h>

// Problem constants (z: [32,4096,256] fp32, embed: [1024,256] fp32)
#define D_DIM   256
#define K_CODES 1024
#define MAX_N   131072

__device__ float  g_cnorm[K_CODES * D_DIM];   // normalized codebook
__device__ int    g_idx[MAX_N];               // argmax indices
__device__ int    g_counts[K_CODES];          // histogram
__device__ double g_partials[MAX_N / 128];    // per-block sq-diff sums

__device__ __forceinline__ void fma2(unsigned long long& d,
                                     unsigned long long a,
                                     unsigned long long b) {
    asm("fma.rn.f32x2 %0, %1, %2, %0;" : "+l"(d) : "l"(a), "l"(b));
}

__device__ __forceinline__ float2 unpack2(unsigned long long v) {
    float2 f;
    asm("mov.b64 {%0, %1}, %2;" : "=f"(f.x), "=f"(f.y) : "l"(v));
    return f;
}

// ---------------------------------------------------------------------------
// Kernel 1: normalize codebook rows (warp per row), zero histogram.
// ---------------------------------------------------------------------------
__global__ __launch_bounds__(256) void vq_prep_kernel(const float* __restrict__ w) {
    const int tid  = threadIdx.x;
    const int lane = tid & 31;
    const int row  = blockIdx.x * 8 + (tid >> 5);

    if (blockIdx.x < 4) g_counts[blockIdx.x * 256 + tid] = 0;

    const float4* W = (const float4*)(w + (long long)row * D_DIM);
    float4 a = W[lane * 2];
    float4 b = W[lane * 2 + 1];
    float s = a.x * a.x + a.y * a.y + a.z * a.z + a.w * a.w +
              b.x * b.x + b.y * b.y + b.z * b.z + b.w * b.w;
#pragma unroll
    for (int off = 16; off > 0; off >>= 1)
        s += __shfl_xor_sync(0xffffffffu, s, off);

    float inv = 1.0f / fmaxf(sqrtf(s), 1e-12f);
    float4* C = (float4*)(g_cnorm + (long long)row * D_DIM);
    a.x *= inv; a.y *= inv; a.z *= inv; a.w *= inv;
    b.x *= inv; b.y *= inv; b.z *= inv; b.w *= inv;
    C[lane * 2]     = a;
    C[lane * 2 + 1] = b;
}

// ---------------------------------------------------------------------------
// Kernel 2: argmax over codes. 256 threads, tile = 128 tokens x 128 codes,
// K-chunk 32, 8x8 micro-tile per thread in packed f32x2.
// Thread map: tx = tid&15 (codes, interleaved stride 16), ty = tid>>4 (tokens).
// ---------------------------------------------------------------------------
#define SROW 34   // smem row stride (floats): 34%32=2 -> conflict-free lanes

__global__ __launch_bounds__(256, 1) void vq_argmax_kernel(
    const float* __restrict__ z, float* __restrict__ out_idx_f, int write_idx)
{
    __shared__ float zs[128 * SROW];
    __shared__ float cs[128 * SROW];

    const int tid   = threadIdx.x;
    const int tx    = tid & 15;
    const int ty    = tid >> 4;
    const int r     = tid >> 1;          // tile row loaded by this thread
    const int halfo = (tid & 1) * 16;    // which 16-col half of the 32-chunk
    const long long zbase = (long long)blockIdx.x * 128 * D_DIM;

    float bv[8];
    int   bi[8];
#pragma unroll
    for (int i = 0; i < 8; i++) { bv[i] = -3.402823466e38f; bi[i] = 0; }

#pragma unroll 1
    for (int ct = 0; ct < 8; ct++) {            // code tiles of 128
        unsigned long long acc[8][8];
#pragma unroll
        for (int i = 0; i < 8; i++)
#pragma unroll
            for (int j = 0; j < 8; j++) acc[i][j] = 0ull;

#pragma unroll 1
        for (int dc = 0; dc < 8; dc++) {        // D chunks of 32
            __syncthreads();
            const float* zg = z + zbase + (long long)r * D_DIM + dc * 32 + halfo;
            const float* cg = g_cnorm + (long long)(ct * 128 + r) * D_DIM + dc * 32 + halfo;
            float* zrow = &zs[r * SROW + halfo];
            float* crow = &cs[r * SROW + halfo];
#pragma unroll
            for (int q = 0; q < 4; q++) {
                float4 v = *(const float4*)(zg + 4 * q);
                *(float2*)(zrow + 4 * q)     = make_float2(v.x, v.y);
                *(float2*)(zrow + 4 * q + 2) = make_float2(v.z, v.w);
                float4 c = *(const float4*)(cg + 4 * q);
                *(float2*)(crow + 4 * q)     = make_float2(c.x, c.y);
                *(float2*)(crow + 4 * q + 2) = make_float2(c.z, c.w);
            }
            __syncthreads();

#pragma unroll
            for (int d2 = 0; d2 < 16; d2++) {
                unsigned long long za[8], ca[8];
#pragma unroll
                for (int i = 0; i < 8; i++)
                    za[i] = *(const unsigned long long*)&zs[(ty + 16 * i) * SROW + 2 * d2];
#pragma unroll
                for (int j = 0; j < 8; j++)
                    ca[j] = *(const unsigned long long*)&cs[(tx + 16 * j) * SROW + 2 * d2];
#pragma unroll
                for (int i = 0; i < 8; i++)
#pragma unroll
                    for (int j = 0; j < 8; j++)
                        fma2(acc[i][j], za[i], ca[j]);
            }
        }

        // fold packed halves, update running best (first-index tie-break)
#pragma unroll
        for (int j = 0; j < 8; j++) {
            const int k = ct * 128 + tx + 16 * j;
#pragma unroll
            for (int i = 0; i < 8; i++) {
                float2 f = unpack2(acc[i][j]);
                float v = f.x + f.y;
                if (v > bv[i] || (v == bv[i] && k < bi[i])) { bv[i] = v; bi[i] = k; }
            }
        }
    }

    // reduce across the 16 tx lanes (xor butterfly, width 16)
#pragma unroll
    for (int i = 0; i < 8; i++) {
        float v = bv[i];
        int   k = bi[i];
#pragma unroll
        for (int off = 8; off > 0; off >>= 1) {
            float ov = __shfl_xor_sync(0xffffffffu, v, off, 16);
            int   ok = __shfl_xor_sync(0xffffffffu, k, off, 16);
            if (ov > v || (ov == v && ok < k)) { v = ov; k = ok; }
        }
        if (tx == 0) {
            const int tok = blockIdx.x * 128 + ty + 16 * i;
            g_idx[tok] = k;
            if (write_idx) out_idx_f[tok] = (float)k;
            atomicAdd(&g_counts[k], 1);
        }
    }
}

// ---------------------------------------------------------------------------
// Kernel 3: gather z_q = embed[idx] and accumulate sum((z_q - z)^2).
// Warp handles 16 tokens (8 floats/lane). Block = 128 tokens.
// ---------------------------------------------------------------------------
__global__ __launch_bounds__(256) void vq_gather_kernel(
    const float* __restrict__ z, const float* __restrict__ w,
    float* __restrict__ zq)
{
    const int tid  = threadIdx.x;
    const int warp = tid >> 5;
    const int lane = tid & 31;
    const int tok0 = blockIdx.x * 128 + warp * 16;

    float acc = 0.f;
#pragma unroll 1
    for (int t = 0; t < 16; t++) {
        const int tok = tok0 + t;
        const int k = g_idx[tok];
        const float4* W = (const float4*)(w + (long long)k * D_DIM);
        const float4* Z = (const float4*)(z + (long long)tok * D_DIM);
        float4*       Q = (float4*)(zq + (long long)tok * D_DIM);
        float4 a = W[lane * 2],     za = Z[lane * 2];
        float4 b = W[lane * 2 + 1], zb = Z[lane * 2 + 1];
        Q[lane * 2]     = a;
        Q[lane * 2 + 1] = b;
        float dx;
        dx = a.x - za.x; acc += dx * dx;
        dx = a.y - za.y; acc += dx * dx;
        dx = a.z - za.z; acc += dx * dx;
        dx = a.w - za.w; acc += dx * dx;
        dx = b.x - zb.x; acc += dx * dx;
        dx = b.y - zb.y; acc += dx * dx;
        dx = b.z - zb.z; acc += dx * dx;
        dx = b.w - zb.w; acc += dx * dx;
    }
#pragma unroll
    for (int off = 16; off > 0; off >>= 1)
        acc += __shfl_xor_sync(0xffffffffu, acc, off);

    __shared__ float sh[8];
    if (lane == 0) sh[warp] = acc;
    __syncthreads();
    if (tid == 0) {
        float s = 0.f;
#pragma unroll
        for (int i = 0; i < 8; i++) s += sh[i];
        g_partials[blockIdx.x] = (double)s;
    }
}

// ---------------------------------------------------------------------------
// Kernel 4: finalize loss + perplexity.
// ---------------------------------------------------------------------------
__global__ __launch_bounds__(256) void vq_finalize_kernel(
    float* __restrict__ out, long long Nz, int N, int nPart)
{
    __shared__ double sh[256];
    const int tid = threadIdx.x;

    double s = 0.0;
    for (int i = tid; i < nPart; i += 256) s += g_partials[i];
    sh[tid] = s;
    __syncthreads();
    for (int st = 128; st > 0; st >>= 1) {
        if (tid < st) sh[tid] += sh[tid + st];
        __syncthreads();
    }
    const double total = sh[0];
    __syncthreads();

    float e = 0.f;
    for (int b = tid; b < K_CODES; b += 256) {
        float p = (float)g_counts[b] / (float)N;
        e += p * logf(p + 1e-10f);
    }
    sh[tid] = (double)e;
    __syncthreads();
    for (int st = 128; st > 0; st >>= 1) {
        if (tid < st) sh[tid] += sh[tid + st];
        __syncthreads();
    }
    if (tid == 0) {
        out[Nz]     = (float)(1.25 * total / ((double)N * (double)D_DIM));
        out[Nz + 1] = expf(-(float)sh[0]);
    }
}

// ---------------------------------------------------------------------------
extern "C" void kernel_launch(void* const* d_in, const int* in_sizes, int n_in,
                              void* d_out, int out_size)
{
    const float* z = (const float*)d_in[0];
    const float* w = (const float*)d_in[1];
    float* out = (float*)d_out;

    const int Nz = in_sizes[0];      // 33554432
    const int N  = Nz / D_DIM;       // 131072 tokens
    const int nBlk = N / 128;        // 1024

    const int write_idx = (out_size >= Nz + 2 + N) ? 1 : 0;

    vq_prep_kernel<<<K_CODES / 8, 256>>>(w);
    vq_argmax_kernel<<<nBlk, 256>>>(z, out + (size_t)Nz + 2, write_idx);
    vq_gather_kernel<<<nBlk, 256>>>(z, w, out);
    vq_finalize_kernel<<<1, 256>>>(out, (long long)Nz, N, nBlk);
}

// round 5
// speedup vs baseline: 2.1033x; 2.1033x over previous
#include <cuda_runtime.h>
#include <cuda_bf16.h>
#include <stdint.h>
#include <math.h>

// Problem constants (z: [32,4096,256] fp32, embed: [1024,256] fp32)
#define D_DIM   256
#define K_CODES 1024
#define MAX_N   131072

// ---------------------------------------------------------------------------
// Device globals (no cudaMalloc allowed)
// ---------------------------------------------------------------------------
__device__ __nv_bfloat16 g_cb_hi[K_CODES * D_DIM];  // normalized codebook, hi, pre-swizzled
__device__ __nv_bfloat16 g_cb_lo[K_CODES * D_DIM];  // normalized codebook, lo, pre-swizzled
__device__ float  g_cnormf[K_CODES * D_DIM];        // normalized codebook fp32 (for rescore)
__device__ int2   g_top2[MAX_N];                    // top-2 candidate indices per token
__device__ int    g_counts[K_CODES];
__device__ double g_partials[MAX_N / 128];

// ---------------------------------------------------------------------------
// PTX helpers (base sm_103 target: ldmatrix + mma.sync only)
// ---------------------------------------------------------------------------
__device__ __forceinline__ uint32_t smem_to_u32(const void* p) {
    uint32_t a;
    asm("{ .reg .u64 t; cvta.to.shared.u64 t, %1; cvt.u32.u64 %0, t; }" : "=r"(a) : "l"(p));
    return a;
}
__device__ __forceinline__ void ldm4(uint32_t* r, uint32_t addr) {
    asm volatile("ldmatrix.sync.aligned.m8n8.x4.shared.b16 {%0,%1,%2,%3}, [%4];"
        : "=r"(r[0]), "=r"(r[1]), "=r"(r[2]), "=r"(r[3]) : "r"(addr));
}
__device__ __forceinline__ void mma16816(float* d, const uint32_t* a,
                                         const uint32_t* b) {
    asm volatile("mma.sync.aligned.m16n8k16.row.col.f32.bf16.bf16.f32 "
        "{%0,%1,%2,%3}, {%4,%5,%6,%7}, {%8,%9}, {%0,%1,%2,%3};"
        : "+f"(d[0]), "+f"(d[1]), "+f"(d[2]), "+f"(d[3])
        : "r"(a[0]), "r"(a[1]), "r"(a[2]), "r"(a[3]), "r"(b[0]), "r"(b[1]));
}

// "a better than b" with first-index tie-break
__device__ __forceinline__ bool better(float av, int ai, float bv, int bi) {
    return (av > bv) || (av == bv && ai < bi);
}
// merge top-2 list (v1,i1,v2,i2) with other top-2 list (w1,j1,w2,j2)
__device__ __forceinline__ void merge_top2(float& v1, int& i1, float& v2, int& i2,
                                           float w1, int j1, float w2, int j2) {
    if (better(w1, j1, v1, i1)) {
        // other list wins top: new second = better(old best, other's second)
        float s2v; int s2i;
        if (better(v1, i1, w2, j2)) { s2v = v1; s2i = i1; }
        else                        { s2v = w2; s2i = j2; }
        v1 = w1; i1 = j1; v2 = s2v; i2 = s2i;
    } else if (better(w1, j1, v2, i2)) {
        v2 = w1; i2 = j1;
    }
}

// hi/lo bf16 split of 8 floats, packed to two uint4
__device__ __forceinline__ void split8(float4 v0, float4 v1, uint4& hp, uint4& lp) {
    float f[8] = {v0.x, v0.y, v0.z, v0.w, v1.x, v1.y, v1.z, v1.w};
    unsigned hs[8], ls[8];
#pragma unroll
    for (int i = 0; i < 8; i++) {
        __nv_bfloat16 h = __float2bfloat16_rn(f[i]);
        __nv_bfloat16 l = __float2bfloat16_rn(f[i] - __bfloat162float(h));
        hs[i] = (unsigned)__bfloat16_as_ushort(h);
        ls[i] = (unsigned)__bfloat16_as_ushort(l);
    }
    hp = make_uint4(hs[0] | (hs[1] << 16), hs[2] | (hs[3] << 16),
                    hs[4] | (hs[5] << 16), hs[6] | (hs[7] << 16));
    lp = make_uint4(ls[0] | (ls[1] << 16), ls[2] | (ls[3] << 16),
                    ls[4] | (ls[5] << 16), ls[6] | (ls[7] << 16));
}

// ---------------------------------------------------------------------------
// Kernel 1: normalize codebook rows; write fp32 copy + hi/lo bf16 pre-swizzled.
// ---------------------------------------------------------------------------
__global__ __launch_bounds__(256) void vq_prep_kernel(const float* __restrict__ w) {
    const int tid  = threadIdx.x;
    const int lane = tid & 31;
    const int row  = blockIdx.x * 8 + (tid >> 5);

    if (blockIdx.x < 4) g_counts[blockIdx.x * 256 + tid] = 0;

    const float4* W = (const float4*)(w + (long long)row * D_DIM);
    float4 a = W[lane * 2];
    float4 b = W[lane * 2 + 1];
    float s = a.x * a.x + a.y * a.y + a.z * a.z + a.w * a.w +
              b.x * b.x + b.y * b.y + b.z * b.z + b.w * b.w;
#pragma unroll
    for (int off = 16; off > 0; off >>= 1)
        s += __shfl_xor_sync(0xffffffffu, s, off);
    float inv = 1.0f / fmaxf(sqrtf(s), 1e-12f);

    a.x *= inv; a.y *= inv; a.z *= inv; a.w *= inv;
    b.x *= inv; b.y *= inv; b.z *= inv; b.w *= inv;

    float4* CF = (float4*)(g_cnormf + (long long)row * D_DIM);
    CF[lane * 2]     = a;
    CF[lane * 2 + 1] = b;

    uint4 hp, lp;
    split8(a, b, hp, lp);
    const int kc  = lane >> 3;                              // K-chunk of 64
    const int swb = (((lane & 7) * 16) ^ ((row & 7) << 4)); // swizzled byte col
    const long long base = ((long long)(kc * 1024 + row)) * 64 + (swb >> 1);
    *(uint4*)&g_cb_hi[base] = hp;
    *(uint4*)&g_cb_lo[base] = lp;
}

// ---------------------------------------------------------------------------
// Kernel 2: HMMA top-2. CTA = 128 tokens x 1024 codes, K=256 (4 chunks of 64).
// 8 warps, grid 2(M) x 4(N), warp tile 64x32, m16n8k16 bf16 mma, split-precision
// 3-product accumulate. Top-2 candidates tracked per token.
// ---------------------------------------------------------------------------
#define A_HI_OFF 0
#define A_LO_OFF 65536
#define B_HI_OFF 131072
#define B_LO_OFF (131072 + 16384)
#define SMEM_SZ  (131072 + 32768)

__global__ __launch_bounds__(256, 1) void vq_argmax_mma_kernel(
    const float* __restrict__ z)
{
    extern __shared__ char smem[];
    const uint32_t sb  = smem_to_u32(smem);
    const int tid  = threadIdx.x;
    const int wid  = tid >> 5;
    const int l    = tid & 31;
    const int wm   = wid >> 2;   // 0..1 : rows [wm*64, +64)
    const int wn   = wid & 3;    // 0..3 : cols [wn*32, +32) within tile

    // ---- A fill: 128 tokens x 256, split hi/lo, SW128 swizzled, 4 K-chunks ----
    {
        const long long zbase = (long long)blockIdx.x * 128 * D_DIM;
#pragma unroll 1
        for (int r = wid; r < 128; r += 8) {
            const float4* Z = (const float4*)(z + zbase + (long long)r * D_DIM);
            float4 v0 = Z[2 * l], v1 = Z[2 * l + 1];
            uint4 hp, lp;
            split8(v0, v1, hp, lp);
            const int kc  = l >> 3;
            const int swb = (((l & 7) * 16) ^ ((r & 7) << 4));
            const int off = kc * 16384 + r * 128 + swb;
            *(uint4*)(smem + A_HI_OFF + off) = hp;
            *(uint4*)(smem + A_LO_OFF + off) = lp;
        }
    }

    // ldmatrix per-lane address constants
    const int arow = l & 15;                 // A row within 16-row tile
    const int akb  = (l & 16) ? 16 : 0;      // A k-byte half
    int aso[4], axr[4];
#pragma unroll
    for (int mt = 0; mt < 4; mt++) {
        const int rowA = wm * 64 + mt * 16 + arow;
        aso[mt] = rowA * 128;
        axr[mt] = (rowA & 7) << 4;
    }
    const int nB  = (l & 7) + ((l & 16) ? 8 : 0);  // B n-row within 16
    const int bkb = (l & 8) ? 16 : 0;              // B k-byte half
    int bso[2], bxr[2];
#pragma unroll
    for (int np = 0; np < 2; np++) {
        const int nrow = wn * 32 + np * 16 + nB;
        bso[np] = nrow * 128;
        bxr[np] = (nrow & 7) << 4;
    }

    float bv1[8], bv2[8];
    int   bi1[8], bi2[8];
#pragma unroll
    for (int s = 0; s < 8; s++) {
        bv1[s] = -3.402823466e38f; bi1[s] = 0;
        bv2[s] = -3.402823466e38f; bi2[s] = 0;
    }

#pragma unroll 1
    for (int nt = 0; nt < 8; nt++) {              // code tiles of 128
        float d[4][4][4];
#pragma unroll
        for (int mt = 0; mt < 4; mt++)
#pragma unroll
            for (int j = 0; j < 4; j++)
#pragma unroll
                for (int q = 0; q < 4; q++) d[mt][j][q] = 0.f;

#pragma unroll 1
        for (int kc = 0; kc < 4; kc++) {          // K chunks of 64
            __syncthreads();   // prior compute done before B overwrite
            {
                const long long srcb = ((long long)(kc * 1024 + nt * 128)) * 64;
                const uint4* sh = (const uint4*)&g_cb_hi[srcb];
                const uint4* sl = (const uint4*)&g_cb_lo[srcb];
                uint4* dh = (uint4*)(smem + B_HI_OFF);
                uint4* dl = (uint4*)(smem + B_LO_OFF);
#pragma unroll
                for (int i = 0; i < 4; i++) {
                    dh[tid + i * 256] = sh[tid + i * 256];
                    dl[tid + i * 256] = sl[tid + i * 256];
                }
            }
            __syncthreads();

            const uint32_t aBaseH = sb + A_HI_OFF + kc * 16384;
            const uint32_t aBaseL = sb + A_LO_OFF + kc * 16384;
#pragma unroll
            for (int ks = 0; ks < 4; ks++) {      // k16 steps within 64
                uint32_t ah[4][4], al[4][4];
#pragma unroll
                for (int mt = 0; mt < 4; mt++) {
                    const uint32_t aoff = aso[mt] + ((ks * 32 + akb) ^ axr[mt]);
                    ldm4(ah[mt], aBaseH + aoff);
                    ldm4(al[mt], aBaseL + aoff);
                }
#pragma unroll
                for (int np = 0; np < 2; np++) {
                    uint32_t bh[4], bl[4];
                    const uint32_t boff = bso[np] + ((ks * 32 + bkb) ^ bxr[np]);
                    ldm4(bh, sb + B_HI_OFF + boff);
                    ldm4(bl, sb + B_LO_OFF + boff);
#pragma unroll
                    for (int mt = 0; mt < 4; mt++) {
                        mma16816(d[mt][np * 2],     ah[mt], bh);       // hi*hi
                        mma16816(d[mt][np * 2],     ah[mt], bl);       // hi*lo
                        mma16816(d[mt][np * 2],     al[mt], bh);       // lo*hi
                        mma16816(d[mt][np * 2 + 1], ah[mt], bh + 2);
                        mma16816(d[mt][np * 2 + 1], ah[mt], bl + 2);
                        mma16816(d[mt][np * 2 + 1], al[mt], bh + 2);
                    }
                }
            }
        }

        // fold 128 codes of this tile into running top-2 (ascending code order)
#pragma unroll
        for (int mt = 0; mt < 4; mt++)
#pragma unroll
            for (int h = 0; h < 2; h++) {
                const int s = mt * 2 + h;
#pragma unroll
                for (int n8 = 0; n8 < 4; n8++)
#pragma unroll
                    for (int j = 0; j < 2; j++) {
                        const float v = d[mt][n8][h * 2 + j];
                        const int   k = nt * 128 + wn * 32 + n8 * 8 + 2 * (l & 3) + j;
                        if (v > bv1[s]) {
                            bv2[s] = bv1[s]; bi2[s] = bi1[s];
                            bv1[s] = v;      bi1[s] = k;
                        } else if (v > bv2[s]) {
                            bv2[s] = v; bi2[s] = k;
                        }
                    }
            }
    }

    __syncthreads();   // compute done; reuse smem for reduction
    float* srv1 = (float*)smem;               // [128][4]
    int*   sri1 = (int*)(smem + 2048);
    float* srv2 = (float*)(smem + 4096);
    int*   sri2 = (int*)(smem + 6144);

#pragma unroll
    for (int mt = 0; mt < 4; mt++)
#pragma unroll
        for (int h = 0; h < 2; h++) {
            const int s = mt * 2 + h;
            float v1 = bv1[s], v2 = bv2[s];
            int   i1 = bi1[s], i2 = bi2[s];
#pragma unroll
            for (int off = 1; off <= 2; off <<= 1) {
                const float w1 = __shfl_xor_sync(0xffffffffu, v1, off);
                const int   j1 = __shfl_xor_sync(0xffffffffu, i1, off);
                const float w2 = __shfl_xor_sync(0xffffffffu, v2, off);
                const int   j2 = __shfl_xor_sync(0xffffffffu, i2, off);
                merge_top2(v1, i1, v2, i2, w1, j1, w2, j2);
            }
            if ((l & 3) == 0) {
                const int row = wm * 64 + mt * 16 + (l >> 2) + 8 * h;
                srv1[row * 4 + wn] = v1; sri1[row * 4 + wn] = i1;
                srv2[row * 4 + wn] = v2; sri2[row * 4 + wn] = i2;
            }
        }
    __syncthreads();

    if (tid < 128) {
        float v1 = srv1[tid * 4], v2 = srv2[tid * 4];
        int   i1 = sri1[tid * 4], i2 = sri2[tid * 4];
#pragma unroll
        for (int e = 1; e < 4; e++)
            merge_top2(v1, i1, v2, i2,
                       srv1[tid * 4 + e], sri1[tid * 4 + e],
                       srv2[tid * 4 + e], sri2[tid * 4 + e]);
        g_top2[blockIdx.x * 128 + tid] = make_int2(i1, i2);
    }
}

// ---------------------------------------------------------------------------
// Kernel 3: fp32 rescore of top-2, gather z_q = embed[k], loss partial,
// histogram, index output.
// ---------------------------------------------------------------------------
__global__ __launch_bounds__(256) void vq_gather_kernel(
    const float* __restrict__ z, const float* __restrict__ w,
    float* __restrict__ zq, float* __restrict__ out_idx_f, int write_idx)
{
    const int tid  = threadIdx.x;
    const int warp = tid >> 5;
    const int lane = tid & 31;
    const int tok0 = blockIdx.x * 128 + warp * 16;

    float acc = 0.f;
#pragma unroll 1
    for (int t = 0; t < 16; t++) {
        const int tok = tok0 + t;
        const int2 c = g_top2[tok];
        const float4* Z = (const float4*)(z + (long long)tok * D_DIM);
        const float4 za = Z[lane * 2], zb = Z[lane * 2 + 1];

        const float4* C1 = (const float4*)(g_cnormf + (long long)c.x * D_DIM);
        const float4* C2 = (const float4*)(g_cnormf + (long long)c.y * D_DIM);
        float4 p = C1[lane * 2], q = C1[lane * 2 + 1];
        float d1 = za.x * p.x + za.y * p.y + za.z * p.z + za.w * p.w +
                   zb.x * q.x + zb.y * q.y + zb.z * q.z + zb.w * q.w;
        p = C2[lane * 2]; q = C2[lane * 2 + 1];
        float d2 = za.x * p.x + za.y * p.y + za.z * p.z + za.w * p.w +
                   zb.x * q.x + zb.y * q.y + zb.z * q.z + zb.w * q.w;
#pragma unroll
        for (int off = 16; off > 0; off >>= 1) {
            d1 += __shfl_xor_sync(0xffffffffu, d1, off);
            d2 += __shfl_xor_sync(0xffffffffu, d2, off);
        }
        const int k = (d2 > d1 || (d2 == d1 && c.y < c.x)) ? c.y : c.x;

        const float4* W = (const float4*)(w + (long long)k * D_DIM);
        float4*       Q = (float4*)(zq + (long long)tok * D_DIM);
        const float4 a = W[lane * 2], b = W[lane * 2 + 1];
        Q[lane * 2]     = a;
        Q[lane * 2 + 1] = b;
        float dx;
        dx = a.x - za.x; acc += dx * dx;
        dx = a.y - za.y; acc += dx * dx;
        dx = a.z - za.z; acc += dx * dx;
        dx = a.w - za.w; acc += dx * dx;
        dx = b.x - zb.x; acc += dx * dx;
        dx = b.y - zb.y; acc += dx * dx;
        dx = b.z - zb.z; acc += dx * dx;
        dx = b.w - zb.w; acc += dx * dx;

        if (lane == 0) {
            atomicAdd(&g_counts[k], 1);
            if (write_idx) out_idx_f[tok] = (float)k;
        }
    }
#pragma unroll
    for (int off = 16; off > 0; off >>= 1)
        acc += __shfl_xor_sync(0xffffffffu, acc, off);

    __shared__ float sh[8];
    if (lane == 0) sh[warp] = acc;
    __syncthreads();
    if (tid == 0) {
        float s = 0.f;
#pragma unroll
        for (int i = 0; i < 8; i++) s += sh[i];
        g_partials[blockIdx.x] = (double)s;
    }
}

// ---------------------------------------------------------------------------
// Kernel 4: finalize loss + perplexity.
// ---------------------------------------------------------------------------
__global__ __launch_bounds__(256) void vq_finalize_kernel(
    float* __restrict__ out, long long Nz, int N, int nPart)
{
    __shared__ double sh[256];
    const int tid = threadIdx.x;

    double s = 0.0;
    for (int i = tid; i < nPart; i += 256) s += g_partials[i];
    sh[tid] = s;
    __syncthreads();
    for (int st = 128; st > 0; st >>= 1) {
        if (tid < st) sh[tid] += sh[tid + st];
        __syncthreads();
    }
    const double total = sh[0];
    __syncthreads();

    float e = 0.f;
    for (int b = tid; b < K_CODES; b += 256) {
        float p = (float)g_counts[b] / (float)N;
        e += p * logf(p + 1e-10f);
    }
    sh[tid] = (double)e;
    __syncthreads();
    for (int st = 128; st > 0; st >>= 1) {
        if (tid < st) sh[tid] += sh[tid + st];
        __syncthreads();
    }
    if (tid == 0) {
        out[Nz]     = (float)(1.25 * total / ((double)N * (double)D_DIM));
        out[Nz + 1] = expf(-(float)sh[0]);
    }
}

// ---------------------------------------------------------------------------
extern "C" void kernel_launch(void* const* d_in, const int* in_sizes, int n_in,
                              void* d_out, int out_size)
{
    const float* z = (const float*)d_in[0];
    const float* w = (const float*)d_in[1];
    float* out = (float*)d_out;

    const int Nz = in_sizes[0];      // 33554432
    const int N  = Nz / D_DIM;       // 131072 tokens
    const int nBlk = N / 128;        // 1024

    const int write_idx = (out_size >= Nz + 2 + N) ? 1 : 0;

    cudaFuncSetAttribute(vq_argmax_mma_kernel,
                         cudaFuncAttributeMaxDynamicSharedMemorySize, SMEM_SZ);

    vq_prep_kernel<<<K_CODES / 8, 256>>>(w);
    vq_argmax_mma_kernel<<<nBlk, 256, SMEM_SZ>>>(z);
    vq_gather_kernel<<<nBlk, 256>>>(z, w, out, out + (size_t)Nz + 2, write_idx);
    vq_finalize_kernel<<<1, 256>>>(out, (long long)Nz, N, nBlk);
}

// round 9
// speedup vs baseline: 2.2000x; 1.0460x over previous
#include <cuda_runtime.h>
#include <cuda_fp16.h>
#include <stdint.h>
#include <math.h>

// Problem constants (z: [32,4096,256] fp32, embed: [1024,256] fp32)
#define D_DIM   256
#define K_CODES 1024
#define MAX_N   131072

// ---------------------------------------------------------------------------
// Device globals (no cudaMalloc allowed)
// ---------------------------------------------------------------------------
__device__ __half  g_cb[K_CODES * D_DIM];      // normalized codebook fp16, pre-swizzled
__device__ float   g_cnormf[K_CODES * D_DIM];  // normalized codebook fp32 (rescore)
__device__ int4    g_top3[MAX_N];              // (i1, i2, i3, gap_as_float_bits)
__device__ int     g_counts[K_CODES];
__device__ double  g_partials[MAX_N / 128];

#define GAP_THRESH 8e-3f

// ---------------------------------------------------------------------------
// PTX helpers (base sm_103 target)
// ---------------------------------------------------------------------------
__device__ __forceinline__ uint32_t smem_to_u32(const void* p) {
    uint32_t a;
    asm("{ .reg .u64 t; cvta.to.shared.u64 t, %1; cvt.u32.u64 %0, t; }" : "=r"(a) : "l"(p));
    return a;
}
__device__ __forceinline__ void ldm4(uint32_t* r, uint32_t addr) {
    asm volatile("ldmatrix.sync.aligned.m8n8.x4.shared.b16 {%0,%1,%2,%3}, [%4];"
        : "=r"(r[0]), "=r"(r[1]), "=r"(r[2]), "=r"(r[3]) : "r"(addr));
}
__device__ __forceinline__ void mma16816(float* d, const uint32_t* a,
                                         const uint32_t* b) {
    asm volatile("mma.sync.aligned.m16n8k16.row.col.f32.f16.f16.f32 "
        "{%0,%1,%2,%3}, {%4,%5,%6,%7}, {%8,%9}, {%0,%1,%2,%3};"
        : "+f"(d[0]), "+f"(d[1]), "+f"(d[2]), "+f"(d[3])
        : "r"(a[0]), "r"(a[1]), "r"(a[2]), "r"(a[3]), "r"(b[0]), "r"(b[1]));
}
__device__ __forceinline__ void cpasync16(uint32_t dst, const void* src) {
    asm volatile("cp.async.cg.shared.global [%0], [%1], 16;" :: "r"(dst), "l"(src));
}
#define CP_COMMIT()  asm volatile("cp.async.commit_group;" ::: "memory")
#define CP_WAIT(n)   asm volatile("cp.async.wait_group %0;" :: "n"(n) : "memory")

// pack two fp32 -> one f16x2 register (lo in low half)
__device__ __forceinline__ uint32_t f2h2(float lo, float hi) {
    uint32_t r;
    asm("cvt.rn.f16x2.f32 %0, %1, %2;" : "=r"(r) : "f"(hi), "f"(lo));
    return r;
}

// "a better than b" with first-index tie-break
__device__ __forceinline__ bool better(float av, int ai, float bv, int bi) {
    return (av > bv) || (av == bv && ai < bi);
}
// insert (v,k) into sorted top-3 (with tie-break)
__device__ __forceinline__ void ins3(float& v1, int& i1, float& v2, int& i2,
                                     float& v3, int& i3, float v, int k) {
    if (better(v, k, v1, i1))      { v3 = v2; i3 = i2; v2 = v1; i2 = i1; v1 = v; i1 = k; }
    else if (better(v, k, v2, i2)) { v3 = v2; i3 = i2; v2 = v; i2 = k; }
    else if (better(v, k, v3, i3)) { v3 = v; i3 = k; }
}

// pack 8 fp32 -> 4 f16x2
__device__ __forceinline__ uint4 pack8h(float4 v0, float4 v1) {
    uint4 o;
    o.x = f2h2(v0.x, v0.y);
    o.y = f2h2(v0.z, v0.w);
    o.z = f2h2(v1.x, v1.y);
    o.w = f2h2(v1.z, v1.w);
    return o;
}

// ---------------------------------------------------------------------------
// Kernel 1: normalize codebook rows; fp32 copy + fp16 pre-swizzled copy.
// Swizzled layout: chunk kc (64 K-elems), code c -> 128-byte row at element
// base (kc*1024 + c)*64; 16-byte groups XOR-swizzled by ((c&7)<<4).
// ---------------------------------------------------------------------------
__global__ __launch_bounds__(256) void vq_prep_kernel(const float* __restrict__ w) {
    const int tid  = threadIdx.x;
    const int lane = tid & 31;
    const int row  = blockIdx.x * 8 + (tid >> 5);

    if (blockIdx.x < 4) g_counts[blockIdx.x * 256 + tid] = 0;

    const float4* W = (const float4*)(w + (long long)row * D_DIM);
    float4 a = W[lane * 2];
    float4 b = W[lane * 2 + 1];
    float s = a.x * a.x + a.y * a.y + a.z * a.z + a.w * a.w +
              b.x * b.x + b.y * b.y + b.z * b.z + b.w * b.w;
#pragma unroll
    for (int off = 16; off > 0; off >>= 1)
        s += __shfl_xor_sync(0xffffffffu, s, off);
    float inv = 1.0f / fmaxf(sqrtf(s), 1e-12f);

    a.x *= inv; a.y *= inv; a.z *= inv; a.w *= inv;
    b.x *= inv; b.y *= inv; b.z *= inv; b.w *= inv;

    float4* CF = (float4*)(g_cnormf + (long long)row * D_DIM);
    CF[lane * 2]     = a;
    CF[lane * 2 + 1] = b;

    const uint4 hp = pack8h(a, b);
    const int kc  = lane >> 3;
    const int swb = (((lane & 7) * 16) ^ ((row & 7) << 4));
    const long long base = ((long long)(kc * 1024 + row)) * 64 + (swb >> 1);
    *(uint4*)&g_cb[base] = hp;
}

// ---------------------------------------------------------------------------
// Kernel 2: single-product fp16 HMMA top-3. CTA = 128 tokens x 1024 codes.
// 8 warps (2M x 4N), warp tile 64x32, K chunks of 64, cp.async double-buffered B.
// ---------------------------------------------------------------------------
#define A_OFF   0
#define B_OFF   65536
#define B_STRIDE 16384
#define SMEM_SZ (65536 + 2 * 16384)

__global__ __launch_bounds__(256, 1) void vq_argmax_mma_kernel(
    const float* __restrict__ z)
{
    extern __shared__ char smem[];
    const uint32_t sb  = smem_to_u32(smem);
    const int tid  = threadIdx.x;
    const int wid  = tid >> 5;
    const int l    = tid & 31;
    const int wm   = wid >> 2;   // 0..1 : rows [wm*64, +64)
    const int wn   = wid & 3;    // 0..3 : cols [wn*32, +32) within tile

    // prefetch B chunk 0 (nt=0, kc=0) while filling A
    {
        const __half* src = g_cb;  // chunk (0,0) at element 0
        const uint32_t dst = sb + B_OFF;
#pragma unroll
        for (int i = 0; i < 4; i++)
            cpasync16(dst + tid * 16 + i * 4096, (const char*)src + tid * 16 + i * 4096);
        CP_COMMIT();
    }

    // ---- A fill: 128 tokens x 256 fp16, SW128 swizzled, 4 K-chunks ----
    {
        const long long zbase = (long long)blockIdx.x * 128 * D_DIM;
#pragma unroll 1
        for (int r = wid; r < 128; r += 8) {
            const float4* Z = (const float4*)(z + zbase + (long long)r * D_DIM);
            const uint4 hp = pack8h(Z[2 * l], Z[2 * l + 1]);
            const int kc  = l >> 3;
            const int swb = (((l & 7) * 16) ^ ((r & 7) << 4));
            *(uint4*)(smem + A_OFF + kc * 16384 + r * 128 + swb) = hp;
        }
    }

    // ldmatrix per-lane address constants
    const int arow = l & 15;
    const int akb  = (l & 16) ? 16 : 0;
    int aso[4], axr[4];
#pragma unroll
    for (int mt = 0; mt < 4; mt++) {
        const int rowA = wm * 64 + mt * 16 + arow;
        aso[mt] = rowA * 128;
        axr[mt] = (rowA & 7) << 4;
    }
    const int nB  = (l & 7) + ((l & 16) ? 8 : 0);
    const int bkb = (l & 8) ? 16 : 0;
    int bso[2], bxr[2];
#pragma unroll
    for (int np = 0; np < 2; np++) {
        const int nrow = wn * 32 + np * 16 + nB;
        bso[np] = nrow * 128;
        bxr[np] = (nrow & 7) << 4;
    }

    float v1[8], v2[8], v3[8];
    int   i1[8], i2[8], i3[8];
#pragma unroll
    for (int s = 0; s < 8; s++) {
        v1[s] = v2[s] = v3[s] = -3.402823466e38f;
        i1[s] = i2[s] = i3[s] = 0;
    }

#pragma unroll 1
    for (int nt = 0; nt < 8; nt++) {              // code tiles of 128
        float d[4][4][4];
#pragma unroll
        for (int mt = 0; mt < 4; mt++)
#pragma unroll
            for (int j = 0; j < 4; j++)
#pragma unroll
                for (int q = 0; q < 4; q++) d[mt][j][q] = 0.f;

#pragma unroll 1
        for (int kc = 0; kc < 4; kc++) {          // K chunks of 64
            const int c   = nt * 4 + kc;
            const int buf = c & 1;
            if (c < 31) {                          // prefetch next chunk
                const int cn  = c + 1;
                const int nt2 = cn >> 2, kc2 = cn & 3;
                const __half* src = g_cb + ((long long)(kc2 * 1024 + nt2 * 128)) * 64;
                const uint32_t dst = sb + B_OFF + (buf ^ 1) * B_STRIDE;
#pragma unroll
                for (int i = 0; i < 4; i++)
                    cpasync16(dst + tid * 16 + i * 4096,
                              (const char*)src + tid * 16 + i * 4096);
                CP_COMMIT();
                CP_WAIT(1);                        // chunk c has landed
            } else {
                CP_WAIT(0);
            }
            __syncthreads();

            const uint32_t aBase = sb + A_OFF + kc * 16384;
            const uint32_t bBase = sb + B_OFF + buf * B_STRIDE;
#pragma unroll
            for (int ks = 0; ks < 4; ks++) {      // k16 steps within 64
                uint32_t ah[4][4];
#pragma unroll
                for (int mt = 0; mt < 4; mt++)
                    ldm4(ah[mt], aBase + aso[mt] + ((ks * 32 + akb) ^ axr[mt]));
#pragma unroll
                for (int np = 0; np < 2; np++) {
                    uint32_t bh[4];
                    ldm4(bh, bBase + bso[np] + ((ks * 32 + bkb) ^ bxr[np]));
#pragma unroll
                    for (int mt = 0; mt < 4; mt++) {
                        mma16816(d[mt][np * 2],     ah[mt], bh);
                        mma16816(d[mt][np * 2 + 1], ah[mt], bh + 2);
                    }
                }
            }
            __syncthreads();   // done reading buf before it is overwritten
        }

        // fold 128 codes of this tile into running top-3 (ascending code order)
#pragma unroll
        for (int mt = 0; mt < 4; mt++)
#pragma unroll
            for (int h = 0; h < 2; h++) {
                const int s = mt * 2 + h;
#pragma unroll
                for (int n8 = 0; n8 < 4; n8++)
#pragma unroll
                    for (int j = 0; j < 2; j++) {
                        const float v = d[mt][n8][h * 2 + j];
                        const int   k = nt * 128 + wn * 32 + n8 * 8 + 2 * (l & 3) + j;
                        ins3(v1[s], i1[s], v2[s], i2[s], v3[s], i3[s], v, k);
                    }
            }
    }

    __syncthreads();   // compute done; reuse smem B region for reduction
    float* sv1 = (float*)(smem + B_OFF);            // [128][4]
    float* sv2 = (float*)(smem + B_OFF + 2048);
    float* sv3 = (float*)(smem + B_OFF + 4096);
    int*   si1 = (int*)(smem + B_OFF + 6144);
    int*   si2 = (int*)(smem + B_OFF + 8192);
    int*   si3 = (int*)(smem + B_OFF + 10240);

#pragma unroll
    for (int mt = 0; mt < 4; mt++)
#pragma unroll
        for (int h = 0; h < 2; h++) {
            const int s = mt * 2 + h;
            float a1 = v1[s], a2 = v2[s], a3 = v3[s];
            int   b1 = i1[s], b2 = i2[s], b3 = i3[s];
#pragma unroll
            for (int off = 1; off <= 2; off <<= 1) {
                const float w1 = __shfl_xor_sync(0xffffffffu, a1, off);
                const int   j1 = __shfl_xor_sync(0xffffffffu, b1, off);
                const float w2 = __shfl_xor_sync(0xffffffffu, a2, off);
                const int   j2 = __shfl_xor_sync(0xffffffffu, b2, off);
                const float w3 = __shfl_xor_sync(0xffffffffu, a3, off);
                const int   j3 = __shfl_xor_sync(0xffffffffu, b3, off);
                ins3(a1, b1, a2, b2, a3, b3, w1, j1);
                ins3(a1, b1, a2, b2, a3, b3, w2, j2);
                ins3(a1, b1, a2, b2, a3, b3, w3, j3);
            }
            if ((l & 3) == 0) {
                const int row = wm * 64 + mt * 16 + (l >> 2) + 8 * h;
                sv1[row * 4 + wn] = a1; si1[row * 4 + wn] = b1;
                sv2[row * 4 + wn] = a2; si2[row * 4 + wn] = b2;
                sv3[row * 4 + wn] = a3; si3[row * 4 + wn] = b3;
            }
        }
    __syncthreads();

    if (tid < 128) {
        float a1 = sv1[tid * 4], a2 = sv2[tid * 4], a3 = sv3[tid * 4];
        int   b1 = si1[tid * 4], b2 = si2[tid * 4], b3 = si3[tid * 4];
#pragma unroll
        for (int e = 1; e < 4; e++) {
            ins3(a1, b1, a2, b2, a3, b3, sv1[tid * 4 + e], si1[tid * 4 + e]);
            ins3(a1, b1, a2, b2, a3, b3, sv2[tid * 4 + e], si2[tid * 4 + e]);
            ins3(a1, b1, a2, b2, a3, b3, sv3[tid * 4 + e], si3[tid * 4 + e]);
        }
        const float gap = a1 - a2;
        g_top3[blockIdx.x * 128 + tid] = make_int4(b1, b2, b3, __float_as_int(gap));
    }
}

// ---------------------------------------------------------------------------
// Kernel 3: conditional fp32 rescore (only if noisy gap small), gather z_q,
// loss partial, histogram, index output.
// ---------------------------------------------------------------------------
__global__ __launch_bounds__(256) void vq_gather_kernel(
    const float* __restrict__ z, const float* __restrict__ w,
    float* __restrict__ zq, float* __restrict__ out_idx_f, int write_idx)
{
    const int tid  = threadIdx.x;
    const int warp = tid >> 5;
    const int lane = tid & 31;
    const int tok0 = blockIdx.x * 128 + warp * 16;

    float acc = 0.f;
#pragma unroll 1
    for (int t = 0; t < 16; t++) {
        const int tok = tok0 + t;
        const int4 c = g_top3[tok];
        const float4* Z = (const float4*)(z + (long long)tok * D_DIM);
        const float4 za = Z[lane * 2], zb = Z[lane * 2 + 1];

        int k = c.x;
        if (__int_as_float(c.w) <= GAP_THRESH) {
            // exact fp32 rescore of the 3 candidates
            float dd[3];
            const int cand[3] = {c.x, c.y, c.z};
#pragma unroll
            for (int e = 0; e < 3; e++) {
                const float4* C = (const float4*)(g_cnormf + (long long)cand[e] * D_DIM);
                const float4 p = C[lane * 2], q = C[lane * 2 + 1];
                dd[e] = za.x * p.x + za.y * p.y + za.z * p.z + za.w * p.w +
                        zb.x * q.x + zb.y * q.y + zb.z * q.z + zb.w * q.w;
            }
#pragma unroll
            for (int off = 16; off > 0; off >>= 1) {
                dd[0] += __shfl_xor_sync(0xffffffffu, dd[0], off);
                dd[1] += __shfl_xor_sync(0xffffffffu, dd[1], off);
                dd[2] += __shfl_xor_sync(0xffffffffu, dd[2], off);
            }
            float bvv = dd[0]; int bii = c.x;
            if (better(dd[1], c.y, bvv, bii)) { bvv = dd[1]; bii = c.y; }
            if (better(dd[2], c.z, bvv, bii)) { bvv = dd[2]; bii = c.z; }
            k = bii;
        }

        const float4* W = (const float4*)(w + (long long)k * D_DIM);
        float4*       Q = (float4*)(zq + (long long)tok * D_DIM);
        const float4 a = W[lane * 2], b = W[lane * 2 + 1];
        Q[lane * 2]     = a;
        Q[lane * 2 + 1] = b;
        float dx;
        dx = a.x - za.x; acc += dx * dx;
        dx = a.y - za.y; acc += dx * dx;
        dx = a.z - za.z; acc += dx * dx;
        dx = a.w - za.w; acc += dx * dx;
        dx = b.x - zb.x; acc += dx * dx;
        dx = b.y - zb.y; acc += dx * dx;
        dx = b.z - zb.z; acc += dx * dx;
        dx = b.w - zb.w; acc += dx * dx;

        if (lane == 0) {
            atomicAdd(&g_counts[k], 1);
            if (write_idx) out_idx_f[tok] = (float)k;
        }
    }
#pragma unroll
    for (int off = 16; off > 0; off >>= 1)
        acc += __shfl_xor_sync(0xffffffffu, acc, off);

    __shared__ float sh[8];
    if (lane == 0) sh[warp] = acc;
    __syncthreads();
    if (tid == 0) {
        float s = 0.f;
#pragma unroll
        for (int i = 0; i < 8; i++) s += sh[i];
        g_partials[blockIdx.x] = (double)s;
    }
}

// ---------------------------------------------------------------------------
// Kernel 4: finalize loss + perplexity.
// ---------------------------------------------------------------------------
__global__ __launch_bounds__(256) void vq_finalize_kernel(
    float* __restrict__ out, long long Nz, int N, int nPart)
{
    __shared__ double sh[256];
    const int tid = threadIdx.x;

    double s = 0.0;
    for (int i = tid; i < nPart; i += 256) s += g_partials[i];
    sh[tid] = s;
    __syncthreads();
    for (int st = 128; st > 0; st >>= 1) {
        if (tid < st) sh[tid] += sh[tid + st];
        __syncthreads();
    }
    const double total = sh[0];
    __syncthreads();

    float e = 0.f;
    for (int b = tid; b < K_CODES; b += 256) {
        float p = (float)g_counts[b] / (float)N;
        e += p * logf(p + 1e-10f);
    }
    sh[tid] = (double)e;
    __syncthreads();
    for (int st = 128; st > 0; st >>= 1) {
        if (tid < st) sh[tid] += sh[tid + st];
        __syncthreads();
    }
    if (tid == 0) {
        out[Nz]     = (float)(1.25 * total / ((double)N * (double)D_DIM));
        out[Nz + 1] = expf(-(float)sh[0]);
    }
}

// ---------------------------------------------------------------------------
extern "C" void kernel_launch(void* const* d_in, const int* in_sizes, int n_in,
                              void* d_out, int out_size)
{
    const float* z = (const float*)d_in[0];
    const float* w = (const float*)d_in[1];
    float* out = (float*)d_out;

    const int Nz = in_sizes[0];      // 33554432
    const int N  = Nz / D_DIM;       // 131072 tokens
    const int nBlk = N / 128;        // 1024

    const int write_idx = (out_size >= Nz + 2 + N) ? 1 : 0;

    cudaFuncSetAttribute(vq_argmax_mma_kernel,
                         cudaFuncAttributeMaxDynamicSharedMemorySize, SMEM_SZ);

    vq_prep_kernel<<<K_CODES / 8, 256>>>(w);
    vq_argmax_mma_kernel<<<nBlk, 256, SMEM_SZ>>>(z);
    vq_gather_kernel<<<nBlk, 256>>>(z, w, out, out + (size_t)Nz + 2, write_idx);
    vq_finalize_kernel<<<1, 256>>>(out, (long long)Nz, N, nBlk);
}

// round 10
// speedup vs baseline: 2.2859x; 1.0391x over previous
#include <cuda_runtime.h>
#include <cuda_fp16.h>
#include <stdint.h>
#include <math.h>

// Problem constants (z: [32,4096,256] fp32, embed: [1024,256] fp32)
#define D_DIM   256
#define K_CODES 1024
#define MAX_N   131072

// ---------------------------------------------------------------------------
// Device globals (no cudaMalloc allowed)
// ---------------------------------------------------------------------------
// g_cb layout: [code_block(8)][kc64(4)][128 codes x 64 elems, SW128 swizzled]
// so one (nt, kchunk128) B chunk = 2 consecutive kc64 blocks = contiguous 32KB.
__device__ __half  g_cb[K_CODES * D_DIM];
__device__ float   g_cnormf[K_CODES * D_DIM];  // normalized codebook fp32 (rescore)
__device__ int4    g_top3[MAX_N];              // (i1, i2, i3, gap_as_float_bits)
__device__ int     g_counts[K_CODES];
__device__ double  g_partials[MAX_N / 128];

#define GAP_THRESH 8e-3f

// ---------------------------------------------------------------------------
// PTX helpers (base sm_103 target)
// ---------------------------------------------------------------------------
__device__ __forceinline__ uint32_t smem_to_u32(const void* p) {
    uint32_t a;
    asm("{ .reg .u64 t; cvta.to.shared.u64 t, %1; cvt.u32.u64 %0, t; }" : "=r"(a) : "l"(p));
    return a;
}
__device__ __forceinline__ void ldm4(uint32_t* r, uint32_t addr) {
    asm volatile("ldmatrix.sync.aligned.m8n8.x4.shared.b16 {%0,%1,%2,%3}, [%4];"
        : "=r"(r[0]), "=r"(r[1]), "=r"(r[2]), "=r"(r[3]) : "r"(addr));
}
__device__ __forceinline__ void mma16816(float* d, const uint32_t* a,
                                         const uint32_t* b) {
    asm volatile("mma.sync.aligned.m16n8k16.row.col.f32.f16.f16.f32 "
        "{%0,%1,%2,%3}, {%4,%5,%6,%7}, {%8,%9}, {%0,%1,%2,%3};"
        : "+f"(d[0]), "+f"(d[1]), "+f"(d[2]), "+f"(d[3])
        : "r"(a[0]), "r"(a[1]), "r"(a[2]), "r"(a[3]), "r"(b[0]), "r"(b[1]));
}
__device__ __forceinline__ void cpasync16(uint32_t dst, const void* src) {
    asm volatile("cp.async.cg.shared.global [%0], [%1], 16;" :: "r"(dst), "l"(src));
}
#define CP_COMMIT()  asm volatile("cp.async.commit_group;" ::: "memory")
#define CP_WAIT(n)   asm volatile("cp.async.wait_group %0;" :: "n"(n) : "memory")

// pack two fp32 -> one f16x2 register (lo in low half)
__device__ __forceinline__ uint32_t f2h2(float lo, float hi) {
    uint32_t r;
    asm("cvt.rn.f16x2.f32 %0, %1, %2;" : "=r"(r) : "f"(hi), "f"(lo));
    return r;
}

// "a better than b" with first-index tie-break
__device__ __forceinline__ bool better(float av, int ai, float bv, int bi) {
    return (av > bv) || (av == bv && ai < bi);
}
// insert (v,k) into sorted top-3 (with tie-break)
__device__ __forceinline__ void ins3(float& v1, int& i1, float& v2, int& i2,
                                     float& v3, int& i3, float v, int k) {
    if (better(v, k, v1, i1))      { v3 = v2; i3 = i2; v2 = v1; i2 = i1; v1 = v; i1 = k; }
    else if (better(v, k, v2, i2)) { v3 = v2; i3 = i2; v2 = v; i2 = k; }
    else if (better(v, k, v3, i3)) { v3 = v; i3 = k; }
}

// pack 8 fp32 -> 4 f16x2
__device__ __forceinline__ uint4 pack8h(float4 v0, float4 v1) {
    uint4 o;
    o.x = f2h2(v0.x, v0.y);
    o.y = f2h2(v0.z, v0.w);
    o.z = f2h2(v1.x, v1.y);
    o.w = f2h2(v1.z, v1.w);
    return o;
}

// ---------------------------------------------------------------------------
// Kernel 1: normalize codebook rows; fp32 copy + fp16 pre-swizzled copy.
// ---------------------------------------------------------------------------
__global__ __launch_bounds__(256) void vq_prep_kernel(const float* __restrict__ w) {
    const int tid  = threadIdx.x;
    const int lane = tid & 31;
    const int row  = blockIdx.x * 8 + (tid >> 5);

    if (blockIdx.x < 4) g_counts[blockIdx.x * 256 + tid] = 0;

    const float4* W = (const float4*)(w + (long long)row * D_DIM);
    float4 a = W[lane * 2];
    float4 b = W[lane * 2 + 1];
    float s = a.x * a.x + a.y * a.y + a.z * a.z + a.w * a.w +
              b.x * b.x + b.y * b.y + b.z * b.z + b.w * b.w;
#pragma unroll
    for (int off = 16; off > 0; off >>= 1)
        s += __shfl_xor_sync(0xffffffffu, s, off);
    float inv = 1.0f / fmaxf(sqrtf(s), 1e-12f);

    a.x *= inv; a.y *= inv; a.z *= inv; a.w *= inv;
    b.x *= inv; b.y *= inv; b.z *= inv; b.w *= inv;

    float4* CF = (float4*)(g_cnormf + (long long)row * D_DIM);
    CF[lane * 2]     = a;
    CF[lane * 2 + 1] = b;

    const uint4 hp = pack8h(a, b);
    const int kc  = lane >> 3;                              // kc64 sub-chunk 0..3
    const int swb = (((lane & 7) * 16) ^ ((row & 7) << 4)); // swizzled byte col
    const int cb  = row >> 7;                               // code block 0..7
    const int cr  = row & 127;                              // row within block
    const long long base = ((long long)(cb * 4 + kc)) * 8192 + cr * 64 + (swb >> 1);
    *(uint4*)&g_cb[base] = hp;
}

// ---------------------------------------------------------------------------
// Kernel 2: single-product fp16 HMMA top-3. CTA = 128 tokens x 1024 codes.
// 8 warps (2M x 4N), warp tile 64x32.
// K-chunks of 128 (32KB B), double-buffered cp.async, ONE barrier per chunk:
//   CP_WAIT(0) -> __syncthreads -> issue prefetch(c+1) -> compute chunk c
// 16 chunks total -> 16 barriers (vs 64 in the previous version).
// ---------------------------------------------------------------------------
#define A_OFF    0
#define B_OFF    65536
#define B_STRIDE 32768
#define SMEM_SZ  (65536 + 2 * 32768)

__global__ __launch_bounds__(256, 1) void vq_argmax_mma_kernel(
    const float* __restrict__ z)
{
    extern __shared__ char smem[];
    const uint32_t sb  = smem_to_u32(smem);
    const int tid  = threadIdx.x;
    const int wid  = tid >> 5;
    const int l    = tid & 31;
    const int wm   = wid >> 2;   // 0..1 : rows [wm*64, +64)
    const int wn   = wid & 3;    // 0..3 : cols [wn*32, +32) within tile

    // prefetch B chunk 0 (nt=0, kchunk=0: g_cb blocks 0..1, 32KB) while filling A
    {
        const uint32_t dst = sb + B_OFF;
#pragma unroll
        for (int i = 0; i < 8; i++)
            cpasync16(dst + tid * 16 + i * 4096, (const char*)g_cb + tid * 16 + i * 4096);
        CP_COMMIT();
    }

    // ---- A fill: 128 tokens x 256 fp16, SW128 swizzled, 4 kc64 sub-chunks ----
    {
        const long long zbase = (long long)blockIdx.x * 128 * D_DIM;
#pragma unroll 1
        for (int r = wid; r < 128; r += 8) {
            const float4* Z = (const float4*)(z + zbase + (long long)r * D_DIM);
            const uint4 hp = pack8h(Z[2 * l], Z[2 * l + 1]);
            const int kc  = l >> 3;
            const int swb = (((l & 7) * 16) ^ ((r & 7) << 4));
            *(uint4*)(smem + A_OFF + kc * 16384 + r * 128 + swb) = hp;
        }
    }

    // ldmatrix per-lane address constants
    const int arow = l & 15;
    const int akb  = (l & 16) ? 16 : 0;
    int aso[4], axr[4];
#pragma unroll
    for (int mt = 0; mt < 4; mt++) {
        const int rowA = wm * 64 + mt * 16 + arow;
        aso[mt] = rowA * 128;
        axr[mt] = (rowA & 7) << 4;
    }
    const int nB  = (l & 7) + ((l & 16) ? 8 : 0);
    const int bkb = (l & 8) ? 16 : 0;
    int bso[2], bxr[2];
#pragma unroll
    for (int np = 0; np < 2; np++) {
        const int nrow = wn * 32 + np * 16 + nB;
        bso[np] = nrow * 128;
        bxr[np] = (nrow & 7) << 4;
    }

    float v1[8], v2[8], v3[8];
    int   i1[8], i2[8], i3[8];
#pragma unroll
    for (int s = 0; s < 8; s++) {
        v1[s] = v2[s] = v3[s] = -3.402823466e38f;
        i1[s] = i2[s] = i3[s] = 0;
    }

#pragma unroll 1
    for (int nt = 0; nt < 8; nt++) {              // code tiles of 128
        float d[4][4][4];
#pragma unroll
        for (int mt = 0; mt < 4; mt++)
#pragma unroll
            for (int j = 0; j < 4; j++)
#pragma unroll
                for (int q = 0; q < 4; q++) d[mt][j][q] = 0.f;

#pragma unroll 1
        for (int kc2 = 0; kc2 < 2; kc2++) {       // K chunks of 128
            const int c   = nt * 2 + kc2;
            const int buf = c & 1;

            CP_WAIT(0);        // own copies of chunk c landed
            __syncthreads();   // everyone's copies landed; prior buf readers done

            if (c < 15) {      // prefetch next 32KB chunk into the other buffer
                const int cn = c + 1;
                const char* src = (const char*)g_cb +
                    ((long long)((cn >> 1) * 4 + (cn & 1) * 2)) * 16384;
                const uint32_t dst = sb + B_OFF + (buf ^ 1) * B_STRIDE;
#pragma unroll
                for (int i = 0; i < 8; i++)
                    cpasync16(dst + tid * 16 + i * 4096, src + tid * 16 + i * 4096);
                CP_COMMIT();
            }

            const uint32_t bBase = sb + B_OFF + buf * B_STRIDE;
#pragma unroll
            for (int ks = 0; ks < 8; ks++) {      // k16 steps within 128
                const int sub = ks >> 2;          // kc64 sub-chunk within 128
                const int ksi = ks & 3;
                const uint32_t aBase = sb + A_OFF + (kc2 * 2 + sub) * 16384;
                uint32_t ah[4][4];
#pragma unroll
                for (int mt = 0; mt < 4; mt++)
                    ldm4(ah[mt], aBase + aso[mt] + ((ksi * 32 + akb) ^ axr[mt]));
#pragma unroll
                for (int np = 0; np < 2; np++) {
                    uint32_t bh[4];
                    ldm4(bh, bBase + sub * 16384 + bso[np] +
                             ((ksi * 32 + bkb) ^ bxr[np]));
#pragma unroll
                    for (int mt = 0; mt < 4; mt++) {
                        mma16816(d[mt][np * 2],     ah[mt], bh);
                        mma16816(d[mt][np * 2 + 1], ah[mt], bh + 2);
                    }
                }
            }
        }

        // fold 128 codes of this tile into running top-3 (ascending code order)
#pragma unroll
        for (int mt = 0; mt < 4; mt++)
#pragma unroll
            for (int h = 0; h < 2; h++) {
                const int s = mt * 2 + h;
#pragma unroll
                for (int n8 = 0; n8 < 4; n8++)
#pragma unroll
                    for (int j = 0; j < 2; j++) {
                        const float v = d[mt][n8][h * 2 + j];
                        const int   k = nt * 128 + wn * 32 + n8 * 8 + 2 * (l & 3) + j;
                        ins3(v1[s], i1[s], v2[s], i2[s], v3[s], i3[s], v, k);
                    }
            }
    }

    __syncthreads();   // compute done; reuse smem B region for reduction
    float* sv1 = (float*)(smem + B_OFF);            // [128][4]
    float* sv2 = (float*)(smem + B_OFF + 2048);
    float* sv3 = (float*)(smem + B_OFF + 4096);
    int*   si1 = (int*)(smem + B_OFF + 6144);
    int*   si2 = (int*)(smem + B_OFF + 8192);
    int*   si3 = (int*)(smem + B_OFF + 10240);

#pragma unroll
    for (int mt = 0; mt < 4; mt++)
#pragma unroll
        for (int h = 0; h < 2; h++) {
            const int s = mt * 2 + h;
            float a1 = v1[s], a2 = v2[s], a3 = v3[s];
            int   b1 = i1[s], b2 = i2[s], b3 = i3[s];
#pragma unroll
            for (int off = 1; off <= 2; off <<= 1) {
                const float w1 = __shfl_xor_sync(0xffffffffu, a1, off);
                const int   j1 = __shfl_xor_sync(0xffffffffu, b1, off);
                const float w2 = __shfl_xor_sync(0xffffffffu, a2, off);
                const int   j2 = __shfl_xor_sync(0xffffffffu, b2, off);
                const float w3 = __shfl_xor_sync(0xffffffffu, a3, off);
                const int   j3 = __shfl_xor_sync(0xffffffffu, b3, off);
                ins3(a1, b1, a2, b2, a3, b3, w1, j1);
                ins3(a1, b1, a2, b2, a3, b3, w2, j2);
                ins3(a1, b1, a2, b2, a3, b3, w3, j3);
            }
            if ((l & 3) == 0) {
                const int row = wm * 64 + mt * 16 + (l >> 2) + 8 * h;
                sv1[row * 4 + wn] = a1; si1[row * 4 + wn] = b1;
                sv2[row * 4 + wn] = a2; si2[row * 4 + wn] = b2;
                sv3[row * 4 + wn] = a3; si3[row * 4 + wn] = b3;
            }
        }
    __syncthreads();

    if (tid < 128) {
        float a1 = sv1[tid * 4], a2 = sv2[tid * 4], a3 = sv3[tid * 4];
        int   b1 = si1[tid * 4], b2 = si2[tid * 4], b3 = si3[tid * 4];
#pragma unroll
        for (int e = 1; e < 4; e++) {
            ins3(a1, b1, a2, b2, a3, b3, sv1[tid * 4 + e], si1[tid * 4 + e]);
            ins3(a1, b1, a2, b2, a3, b3, sv2[tid * 4 + e], si2[tid * 4 + e]);
            ins3(a1, b1, a2, b2, a3, b3, sv3[tid * 4 + e], si3[tid * 4 + e]);
        }
        const float gap = a1 - a2;
        g_top3[blockIdx.x * 128 + tid] = make_int4(b1, b2, b3, __float_as_int(gap));
    }
}

// ---------------------------------------------------------------------------
// Kernel 3: conditional fp32 rescore (only if noisy gap small), gather z_q,
// loss partial, histogram, index output.
// ---------------------------------------------------------------------------
__global__ __launch_bounds__(256) void vq_gather_kernel(
    const float* __restrict__ z, const float* __restrict__ w,
    float* __restrict__ zq, float* __restrict__ out_idx_f, int write_idx)
{
    const int tid  = threadIdx.x;
    const int warp = tid >> 5;
    const int lane = tid & 31;
    const int tok0 = blockIdx.x * 128 + warp * 16;

    float acc = 0.f;
#pragma unroll 1
    for (int t = 0; t < 16; t++) {
        const int tok = tok0 + t;
        const int4 c = g_top3[tok];
        const float4* Z = (const float4*)(z + (long long)tok * D_DIM);
        const float4 za = Z[lane * 2], zb = Z[lane * 2 + 1];

        int k = c.x;
        if (__int_as_float(c.w) <= GAP_THRESH) {
            // exact fp32 rescore of the 3 candidates
            float dd[3];
            const int cand[3] = {c.x, c.y, c.z};
#pragma unroll
            for (int e = 0; e < 3; e++) {
                const float4* C = (const float4*)(g_cnormf + (long long)cand[e] * D_DIM);
                const float4 p = C[lane * 2], q = C[lane * 2 + 1];
                dd[e] = za.x * p.x + za.y * p.y + za.z * p.z + za.w * p.w +
                        zb.x * q.x + zb.y * q.y + zb.z * q.z + zb.w * q.w;
            }
#pragma unroll
            for (int off = 16; off > 0; off >>= 1) {
                dd[0] += __shfl_xor_sync(0xffffffffu, dd[0], off);
                dd[1] += __shfl_xor_sync(0xffffffffu, dd[1], off);
                dd[2] += __shfl_xor_sync(0xffffffffu, dd[2], off);
            }
            float bvv = dd[0]; int bii = c.x;
            if (better(dd[1], c.y, bvv, bii)) { bvv = dd[1]; bii = c.y; }
            if (better(dd[2], c.z, bvv, bii)) { bvv = dd[2]; bii = c.z; }
            k = bii;
        }

        const float4* W = (const float4*)(w + (long long)k * D_DIM);
        float4*       Q = (float4*)(zq + (long long)tok * D_DIM);
        const float4 a = W[lane * 2], b = W[lane * 2 + 1];
        Q[lane * 2]     = a;
        Q[lane * 2 + 1] = b;
        float dx;
        dx = a.x - za.x; acc += dx * dx;
        dx = a.y - za.y; acc += dx * dx;
        dx = a.z - za.z; acc += dx * dx;
        dx = a.w - za.w; acc += dx * dx;
        dx = b.x - zb.x; acc += dx * dx;
        dx = b.y - zb.y; acc += dx * dx;
        dx = b.z - zb.z; acc += dx * dx;
        dx = b.w - zb.w; acc += dx * dx;

        if (lane == 0) {
            atomicAdd(&g_counts[k], 1);
            if (write_idx) out_idx_f[tok] = (float)k;
        }
    }
#pragma unroll
    for (int off = 16; off > 0; off >>= 1)
        acc += __shfl_xor_sync(0xffffffffu, acc, off);

    __shared__ float sh[8];
    if (lane == 0) sh[warp] = acc;
    __syncthreads();
    if (tid == 0) {
        float s = 0.f;
#pragma unroll
        for (int i = 0; i < 8; i++) s += sh[i];
        g_partials[blockIdx.x] = (double)s;
    }
}

// ---------------------------------------------------------------------------
// Kernel 4: finalize loss + perplexity.
// ---------------------------------------------------------------------------
__global__ __launch_bounds__(256) void vq_finalize_kernel(
    float* __restrict__ out, long long Nz, int N, int nPart)
{
    __shared__ double sh[256];
    const int tid = threadIdx.x;

    double s = 0.0;
    for (int i = tid; i < nPart; i += 256) s += g_partials[i];
    sh[tid] = s;
    __syncthreads();
    for (int st = 128; st > 0; st >>= 1) {
        if (tid < st) sh[tid] += sh[tid + st];
        __syncthreads();
    }
    const double total = sh[0];
    __syncthreads();

    float e = 0.f;
    for (int b = tid; b < K_CODES; b += 256) {
        float p = (float)g_counts[b] / (float)N;
        e += p * logf(p + 1e-10f);
    }
    sh[tid] = (double)e;
    __syncthreads();
    for (int st = 128; st > 0; st >>= 1) {
        if (tid < st) sh[tid] += sh[tid + st];
        __syncthreads();
    }
    if (tid == 0) {
        out[Nz]     = (float)(1.25 * total / ((double)N * (double)D_DIM));
        out[Nz + 1] = expf(-(float)sh[0]);
    }
}

// ---------------------------------------------------------------------------
extern "C" void kernel_launch(void* const* d_in, const int* in_sizes, int n_in,
                              void* d_out, int out_size)
{
    const float* z = (const float*)d_in[0];
    const float* w = (const float*)d_in[1];
    float* out = (float*)d_out;

    const int Nz = in_sizes[0];      // 33554432
    const int N  = Nz / D_DIM;       // 131072 tokens
    const int nBlk = N / 128;        // 1024

    const int write_idx = (out_size >= Nz + 2 + N) ? 1 : 0;

    cudaFuncSetAttribute(vq_argmax_mma_kernel,
                         cudaFuncAttributeMaxDynamicSharedMemorySize, SMEM_SZ);

    vq_prep_kernel<<<K_CODES / 8, 256>>>(w);
    vq_argmax_mma_kernel<<<nBlk, 256, SMEM_SZ>>>(z);
    vq_gather_kernel<<<nBlk, 256>>>(z, w, out, out + (size_t)Nz + 2, write_idx);
    vq_finalize_kernel<<<1, 256>>>(out, (long long)Nz, N, nBlk);
}

// round 11
// speedup vs baseline: 3.0523x; 1.3353x over previous
#include <cuda_runtime.h>
#include <cuda_fp16.h>
#include <stdint.h>
#include <math.h>

// Problem constants (z: [32,4096,256] fp32, embed: [1024,256] fp32)
#define D_DIM   256
#define K_CODES 1024
#define MAX_N   131072

// ---------------------------------------------------------------------------
// Device globals (no cudaMalloc allowed)
// ---------------------------------------------------------------------------
// g_cb layout: [code_block(8)][kc64(4)][128 codes x 64 elems, SW128 swizzled]
// so one (nt, kchunk128) B chunk = 2 consecutive kc64 blocks = contiguous 32KB.
__device__ __half  g_cb[K_CODES * D_DIM];
__device__ float   g_cnormf[K_CODES * D_DIM];  // normalized codebook fp32 (rescore)
__device__ int4    g_top3[MAX_N];              // (i1, i2, i3, gap_as_float_bits)
__device__ int     g_counts[K_CODES];
__device__ double  g_partials[MAX_N / 128];

#define GAP_THRESH 8e-3f

// ---------------------------------------------------------------------------
// PTX helpers (base sm_103 target)
// ---------------------------------------------------------------------------
__device__ __forceinline__ uint32_t smem_to_u32(const void* p) {
    uint32_t a;
    asm("{ .reg .u64 t; cvta.to.shared.u64 t, %1; cvt.u32.u64 %0, t; }" : "=r"(a) : "l"(p));
    return a;
}
__device__ __forceinline__ void ldm4(uint32_t* r, uint32_t addr) {
    asm volatile("ldmatrix.sync.aligned.m8n8.x4.shared.b16 {%0,%1,%2,%3}, [%4];"
        : "=r"(r[0]), "=r"(r[1]), "=r"(r[2]), "=r"(r[3]) : "r"(addr));
}
__device__ __forceinline__ void mma16816(float* d, const uint32_t* a,
                                         const uint32_t* b) {
    asm volatile("mma.sync.aligned.m16n8k16.row.col.f32.f16.f16.f32 "
        "{%0,%1,%2,%3}, {%4,%5,%6,%7}, {%8,%9}, {%0,%1,%2,%3};"
        : "+f"(d[0]), "+f"(d[1]), "+f"(d[2]), "+f"(d[3])
        : "r"(a[0]), "r"(a[1]), "r"(a[2]), "r"(a[3]), "r"(b[0]), "r"(b[1]));
}
__device__ __forceinline__ void cpasync16(uint32_t dst, const void* src) {
    asm volatile("cp.async.cg.shared.global [%0], [%1], 16;" :: "r"(dst), "l"(src));
}
#define CP_COMMIT()  asm volatile("cp.async.commit_group;" ::: "memory")
#define CP_WAIT(n)   asm volatile("cp.async.wait_group %0;" :: "n"(n) : "memory")

// pack two fp32 -> one f16x2 register (lo in low half)
__device__ __forceinline__ uint32_t f2h2(float lo, float hi) {
    uint32_t r;
    asm("cvt.rn.f16x2.f32 %0, %1, %2;" : "=r"(r) : "f"(hi), "f"(lo));
    return r;
}

// "a better than b" with first-index tie-break
__device__ __forceinline__ bool better(float av, int ai, float bv, int bi) {
    return (av > bv) || (av == bv && ai < bi);
}
// insert (v,k) into sorted top-3 (with tie-break)
__device__ __forceinline__ void ins3(float& v1, int& i1, float& v2, int& i2,
                                     float& v3, int& i3, float v, int k) {
    if (better(v, k, v1, i1))      { v3 = v2; i3 = i2; v2 = v1; i2 = i1; v1 = v; i1 = k; }
    else if (better(v, k, v2, i2)) { v3 = v2; i3 = i2; v2 = v; i2 = k; }
    else if (better(v, k, v3, i3)) { v3 = v; i3 = k; }
}

// pack 8 fp32 -> 4 f16x2
__device__ __forceinline__ uint4 pack8h(float4 v0, float4 v1) {
    uint4 o;
    o.x = f2h2(v0.x, v0.y);
    o.y = f2h2(v0.z, v0.w);
    o.z = f2h2(v1.x, v1.y);
    o.w = f2h2(v1.z, v1.w);
    return o;
}

// ---------------------------------------------------------------------------
// Kernel 1: normalize codebook rows; fp32 copy + fp16 pre-swizzled copy.
// ---------------------------------------------------------------------------
__global__ __launch_bounds__(256) void vq_prep_kernel(const float* __restrict__ w) {
    const int tid  = threadIdx.x;
    const int lane = tid & 31;
    const int row  = blockIdx.x * 8 + (tid >> 5);

    if (blockIdx.x < 4) g_counts[blockIdx.x * 256 + tid] = 0;

    const float4* W = (const float4*)(w + (long long)row * D_DIM);
    float4 a = W[lane * 2];
    float4 b = W[lane * 2 + 1];
    float s = a.x * a.x + a.y * a.y + a.z * a.z + a.w * a.w +
              b.x * b.x + b.y * b.y + b.z * b.z + b.w * b.w;
#pragma unroll
    for (int off = 16; off > 0; off >>= 1)
        s += __shfl_xor_sync(0xffffffffu, s, off);
    float inv = 1.0f / fmaxf(sqrtf(s), 1e-12f);

    a.x *= inv; a.y *= inv; a.z *= inv; a.w *= inv;
    b.x *= inv; b.y *= inv; b.z *= inv; b.w *= inv;

    float4* CF = (float4*)(g_cnormf + (long long)row * D_DIM);
    CF[lane * 2]     = a;
    CF[lane * 2 + 1] = b;

    const uint4 hp = pack8h(a, b);
    const int kc  = lane >> 3;                              // kc64 sub-chunk 0..3
    const int swb = (((lane & 7) * 16) ^ ((row & 7) << 4)); // swizzled byte col
    const int cb  = row >> 7;                               // code block 0..7
    const int cr  = row & 127;                              // row within block
    const long long base = ((long long)(cb * 4 + kc)) * 8192 + cr * 64 + (swb >> 1);
    *(uint4*)&g_cb[base] = hp;
}

// ---------------------------------------------------------------------------
// Kernel 2: single-product fp16 HMMA top-3. CTA = 128 tokens x 1024 codes.
// 512 threads / 16 warps (4M x 4N), warp tile 32x32 -> 4 warps per SMSP for
// latency hiding. K-chunks of 128 (32KB B), double-buffered cp.async, one
// barrier per chunk. 16 chunks total.
// ---------------------------------------------------------------------------
#define A_OFF    0
#define B_OFF    65536
#define B_STRIDE 32768
#define SMEM_SZ  (65536 + 2 * 32768)
#define NTHR     512

__global__ __launch_bounds__(NTHR, 1) void vq_argmax_mma_kernel(
    const float* __restrict__ z)
{
    extern __shared__ char smem[];
    const uint32_t sb  = smem_to_u32(smem);
    const int tid  = threadIdx.x;
    const int wid  = tid >> 5;   // 0..15
    const int l    = tid & 31;
    const int wm   = wid >> 2;   // 0..3 : rows [wm*32, +32)
    const int wn   = wid & 3;    // 0..3 : cols [wn*32, +32) within tile

    // prefetch B chunk 0 (32KB) while filling A
    {
        const uint32_t dst = sb + B_OFF;
#pragma unroll
        for (int i = 0; i < 4; i++)
            cpasync16(dst + tid * 16 + i * 8192, (const char*)g_cb + tid * 16 + i * 8192);
        CP_COMMIT();
    }

    // ---- A fill: 128 tokens x 256 fp16, SW128 swizzled, 4 kc64 sub-chunks ----
    {
        const long long zbase = (long long)blockIdx.x * 128 * D_DIM;
#pragma unroll 1
        for (int r = wid; r < 128; r += 16) {
            const float4* Z = (const float4*)(z + zbase + (long long)r * D_DIM);
            const uint4 hp = pack8h(Z[2 * l], Z[2 * l + 1]);
            const int kc  = l >> 3;
            const int swb = (((l & 7) * 16) ^ ((r & 7) << 4));
            *(uint4*)(smem + A_OFF + kc * 16384 + r * 128 + swb) = hp;
        }
    }

    // ldmatrix per-lane address constants
    const int arow = l & 15;
    const int akb  = (l & 16) ? 16 : 0;
    int aso[2], axr[2];
#pragma unroll
    for (int mt = 0; mt < 2; mt++) {
        const int rowA = wm * 32 + mt * 16 + arow;
        aso[mt] = rowA * 128;
        axr[mt] = (rowA & 7) << 4;
    }
    const int nB  = (l & 7) + ((l & 16) ? 8 : 0);
    const int bkb = (l & 8) ? 16 : 0;
    int bso[2], bxr[2];
#pragma unroll
    for (int np = 0; np < 2; np++) {
        const int nrow = wn * 32 + np * 16 + nB;
        bso[np] = nrow * 128;
        bxr[np] = (nrow & 7) << 4;
    }

    // top-3 state: 4 row-slots per thread (2 mt x 2 row-halves)
    float v1[4], v2[4], v3[4];
    int   i1[4], i2[4], i3[4];
#pragma unroll
    for (int s = 0; s < 4; s++) {
        v1[s] = v2[s] = v3[s] = -3.402823466e38f;
        i1[s] = i2[s] = i3[s] = 0;
    }

#pragma unroll 1
    for (int nt = 0; nt < 8; nt++) {              // code tiles of 128
        float d[2][4][4];                         // [mt][np*2+half][quad]
#pragma unroll
        for (int mt = 0; mt < 2; mt++)
#pragma unroll
            for (int g = 0; g < 4; g++)
#pragma unroll
                for (int q = 0; q < 4; q++) d[mt][g][q] = 0.f;

#pragma unroll 1
        for (int kc2 = 0; kc2 < 2; kc2++) {       // K chunks of 128
            const int c   = nt * 2 + kc2;
            const int buf = c & 1;

            CP_WAIT(0);        // own copies of chunk c landed
            __syncthreads();   // everyone's copies landed; prior buf readers done

            if (c < 15) {      // prefetch next 32KB chunk into the other buffer
                const int cn = c + 1;
                const char* src = (const char*)g_cb +
                    ((long long)((cn >> 1) * 4 + (cn & 1) * 2)) * 16384;
                const uint32_t dst = sb + B_OFF + (buf ^ 1) * B_STRIDE;
#pragma unroll
                for (int i = 0; i < 4; i++)
                    cpasync16(dst + tid * 16 + i * 8192, src + tid * 16 + i * 8192);
                CP_COMMIT();
            }

            const uint32_t bBase = sb + B_OFF + buf * B_STRIDE;
#pragma unroll
            for (int ks = 0; ks < 8; ks++) {      // k16 steps within 128
                const int sub = ks >> 2;          // kc64 sub-chunk within 128
                const int ksi = ks & 3;
                const uint32_t aBase = sb + A_OFF + (kc2 * 2 + sub) * 16384;
                uint32_t ah[2][4];
#pragma unroll
                for (int mt = 0; mt < 2; mt++)
                    ldm4(ah[mt], aBase + aso[mt] + ((ksi * 32 + akb) ^ axr[mt]));
#pragma unroll
                for (int np = 0; np < 2; np++) {
                    uint32_t bh[4];
                    ldm4(bh, bBase + sub * 16384 + bso[np] +
                             ((ksi * 32 + bkb) ^ bxr[np]));
#pragma unroll
                    for (int mt = 0; mt < 2; mt++) {
                        mma16816(d[mt][np * 2],     ah[mt], bh);
                        mma16816(d[mt][np * 2 + 1], ah[mt], bh + 2);
                    }
                }
            }
        }

        // fold 128 codes of this tile into running top-3 (ascending code order)
#pragma unroll
        for (int mt = 0; mt < 2; mt++)
#pragma unroll
            for (int h = 0; h < 2; h++) {
                const int s = mt * 2 + h;
#pragma unroll
                for (int g = 0; g < 4; g++)
#pragma unroll
                    for (int j = 0; j < 2; j++) {
                        const float v = d[mt][g][h * 2 + j];
                        const int   k = nt * 128 + wn * 32 + g * 8 + 2 * (l & 3) + j;
                        ins3(v1[s], i1[s], v2[s], i2[s], v3[s], i3[s], v, k);
                    }
            }
    }

    __syncthreads();   // compute done; reuse smem B region for reduction
    float* sv1 = (float*)(smem + B_OFF);            // [128][4]
    float* sv2 = (float*)(smem + B_OFF + 2048);
    float* sv3 = (float*)(smem + B_OFF + 4096);
    int*   si1 = (int*)(smem + B_OFF + 6144);
    int*   si2 = (int*)(smem + B_OFF + 8192);
    int*   si3 = (int*)(smem + B_OFF + 10240);

#pragma unroll
    for (int mt = 0; mt < 2; mt++)
#pragma unroll
        for (int h = 0; h < 2; h++) {
            const int s = mt * 2 + h;
            float a1 = v1[s], a2 = v2[s], a3 = v3[s];
            int   b1 = i1[s], b2 = i2[s], b3 = i3[s];
#pragma unroll
            for (int off = 1; off <= 2; off <<= 1) {
                const float w1 = __shfl_xor_sync(0xffffffffu, a1, off);
                const int   j1 = __shfl_xor_sync(0xffffffffu, b1, off);
                const float w2 = __shfl_xor_sync(0xffffffffu, a2, off);
                const int   j2 = __shfl_xor_sync(0xffffffffu, b2, off);
                const float w3 = __shfl_xor_sync(0xffffffffu, a3, off);
                const int   j3 = __shfl_xor_sync(0xffffffffu, b3, off);
                ins3(a1, b1, a2, b2, a3, b3, w1, j1);
                ins3(a1, b1, a2, b2, a3, b3, w2, j2);
                ins3(a1, b1, a2, b2, a3, b3, w3, j3);
            }
            if ((l & 3) == 0) {
                const int row = wm * 32 + mt * 16 + (l >> 2) + 8 * h;
                sv1[row * 4 + wn] = a1; si1[row * 4 + wn] = b1;
                sv2[row * 4 + wn] = a2; si2[row * 4 + wn] = b2;
                sv3[row * 4 + wn] = a3; si3[row * 4 + wn] = b3;
            }
        }
    __syncthreads();

    if (tid < 128) {
        float a1 = sv1[tid * 4], a2 = sv2[tid * 4], a3 = sv3[tid * 4];
        int   b1 = si1[tid * 4], b2 = si2[tid * 4], b3 = si3[tid * 4];
#pragma unroll
        for (int e = 1; e < 4; e++) {
            ins3(a1, b1, a2, b2, a3, b3, sv1[tid * 4 + e], si1[tid * 4 + e]);
            ins3(a1, b1, a2, b2, a3, b3, sv2[tid * 4 + e], si2[tid * 4 + e]);
            ins3(a1, b1, a2, b2, a3, b3, sv3[tid * 4 + e], si3[tid * 4 + e]);
        }
        const float gap = a1 - a2;
        g_top3[blockIdx.x * 128 + tid] = make_int4(b1, b2, b3, __float_as_int(gap));
    }
}

// ---------------------------------------------------------------------------
// Kernel 3: conditional fp32 rescore (only if noisy gap small), gather z_q,
// loss partial, histogram, index output.
// ---------------------------------------------------------------------------
__global__ __launch_bounds__(256) void vq_gather_kernel(
    const float* __restrict__ z, const float* __restrict__ w,
    float* __restrict__ zq, float* __restrict__ out_idx_f, int write_idx)
{
    const int tid  = threadIdx.x;
    const int warp = tid >> 5;
    const int lane = tid & 31;
    const int tok0 = blockIdx.x * 128 + warp * 16;

    float acc = 0.f;
#pragma unroll 1
    for (int t = 0; t < 16; t++) {
        const int tok = tok0 + t;
        const int4 c = g_top3[tok];
        const float4* Z = (const float4*)(z + (long long)tok * D_DIM);
        const float4 za = Z[lane * 2], zb = Z[lane * 2 + 1];

        int k = c.x;
        if (__int_as_float(c.w) <= GAP_THRESH) {
            // exact fp32 rescore of the 3 candidates
            float dd[3];
            const int cand[3] = {c.x, c.y, c.z};
#pragma unroll
            for (int e = 0; e < 3; e++) {
                const float4* C = (const float4*)(g_cnormf + (long long)cand[e] * D_DIM);
                const float4 p = C[lane * 2], q = C[lane * 2 + 1];
                dd[e] = za.x * p.x + za.y * p.y + za.z * p.z + za.w * p.w +
                        zb.x * q.x + zb.y * q.y + zb.z * q.z + zb.w * q.w;
            }
#pragma unroll
            for (int off = 16; off > 0; off >>= 1) {
                dd[0] += __shfl_xor_sync(0xffffffffu, dd[0], off);
                dd[1] += __shfl_xor_sync(0xffffffffu, dd[1], off);
                dd[2] += __shfl_xor_sync(0xffffffffu, dd[2], off);
            }
            float bvv = dd[0]; int bii = c.x;
            if (better(dd[1], c.y, bvv, bii)) { bvv = dd[1]; bii = c.y; }
            if (better(dd[2], c.z, bvv, bii)) { bvv = dd[2]; bii = c.z; }
            k = bii;
        }

        const float4* W = (const float4*)(w + (long long)k * D_DIM);
        float4*       Q = (float4*)(zq + (long long)tok * D_DIM);
        const float4 a = W[lane * 2], b = W[lane * 2 + 1];
        Q[lane * 2]     = a;
        Q[lane * 2 + 1] = b;
        float dx;
        dx = a.x - za.x; acc += dx * dx;
        dx = a.y - za.y; acc += dx * dx;
        dx = a.z - za.z; acc += dx * dx;
        dx = a.w - za.w; acc += dx * dx;
        dx = b.x - zb.x; acc += dx * dx;
        dx = b.y - zb.y; acc += dx * dx;
        dx = b.z - zb.z; acc += dx * dx;
        dx = b.w - zb.w; acc += dx * dx;

        if (lane == 0) {
            atomicAdd(&g_counts[k], 1);
            if (write_idx) out_idx_f[tok] = (float)k;
        }
    }
#pragma unroll
    for (int off = 16; off > 0; off >>= 1)
        acc += __shfl_xor_sync(0xffffffffu, acc, off);

    __shared__ float sh[8];
    if (lane == 0) sh[warp] = acc;
    __syncthreads();
    if (tid == 0) {
        float s = 0.f;
#pragma unroll
        for (int i = 0; i < 8; i++) s += sh[i];
        g_partials[blockIdx.x] = (double)s;
    }
}

// ---------------------------------------------------------------------------
// Kernel 4: finalize loss + perplexity.
// ---------------------------------------------------------------------------
__global__ __launch_bounds__(256) void vq_finalize_kernel(
    float* __restrict__ out, long long Nz, int N, int nPart)
{
    __shared__ double sh[256];
    const int tid = threadIdx.x;

    double s = 0.0;
    for (int i = tid; i < nPart; i += 256) s += g_partials[i];
    sh[tid] = s;
    __syncthreads();
    for (int st = 128; st > 0; st >>= 1) {
        if (tid < st) sh[tid] += sh[tid + st];
        __syncthreads();
    }
    const double total = sh[0];
    __syncthreads();

    float e = 0.f;
    for (int b = tid; b < K_CODES; b += 256) {
        float p = (float)g_counts[b] / (float)N;
        e += p * logf(p + 1e-10f);
    }
    sh[tid] = (double)e;
    __syncthreads();
    for (int st = 128; st > 0; st >>= 1) {
        if (tid < st) sh[tid] += sh[tid + st];
        __syncthreads();
    }
    if (tid == 0) {
        out[Nz]     = (float)(1.25 * total / ((double)N * (double)D_DIM));
        out[Nz + 1] = expf(-(float)sh[0]);
    }
}

// ---------------------------------------------------------------------------
extern "C" void kernel_launch(void* const* d_in, const int* in_sizes, int n_in,
                              void* d_out, int out_size)
{
    const float* z = (const float*)d_in[0];
    const float* w = (const float*)d_in[1];
    float* out = (float*)d_out;

    const int Nz = in_sizes[0];      // 33554432
    const int N  = Nz / D_DIM;       // 131072 tokens
    const int nBlk = N / 128;        // 1024

    const int write_idx = (out_size >= Nz + 2 + N) ? 1 : 0;

    cudaFuncSetAttribute(vq_argmax_mma_kernel,
                         cudaFuncAttributeMaxDynamicSharedMemorySize, SMEM_SZ);

    vq_prep_kernel<<<K_CODES / 8, 256>>>(w);
    vq_argmax_mma_kernel<<<nBlk, NTHR, SMEM_SZ>>>(z);
    vq_gather_kernel<<<nBlk, 256>>>(z, w, out, out + (size_t)Nz + 2, write_idx);
    vq_finalize_kernel<<<1, 256>>>(out, (long long)Nz, N, nBlk);
}

// round 13
// speedup vs baseline: 3.1252x; 1.0239x over previous
#include <cuda_runtime.h>
#include <cuda_fp16.h>
#include <stdint.h>
#include <math.h>

// Problem constants (z: [32,4096,256] fp32, embed: [1024,256] fp32)
#define D_DIM   256
#define K_CODES 1024
#define MAX_N   131072

// ---------------------------------------------------------------------------
// Device globals (no cudaMalloc allowed)
// ---------------------------------------------------------------------------
// g_cb layout: [code_block(8)][kc64(4)][128 codes x 64 elems, SW128 swizzled]
// so one (nt, kchunk128) B chunk = 2 consecutive kc64 blocks = contiguous 32KB.
__device__ __half  g_cb[K_CODES * D_DIM];
__device__ float   g_cnormf[K_CODES * D_DIM];  // normalized codebook fp32 (rescore)
__device__ int4    g_top3[MAX_N];              // (i1, i2, i3, gap_as_float_bits)
__device__ int     g_counts[K_CODES];
__device__ double  g_partials[MAX_N / 128];

#define GAP_THRESH 8e-3f

// ---------------------------------------------------------------------------
// PTX helpers (base sm_103 target)
// ---------------------------------------------------------------------------
__device__ __forceinline__ uint32_t smem_to_u32(const void* p) {
    uint32_t a;
    asm("{ .reg .u64 t; cvta.to.shared.u64 t, %1; cvt.u32.u64 %0, t; }" : "=r"(a) : "l"(p));
    return a;
}
__device__ __forceinline__ void ldm4(uint32_t* r, uint32_t addr) {
    asm volatile("ldmatrix.sync.aligned.m8n8.x4.shared.b16 {%0,%1,%2,%3}, [%4];"
        : "=r"(r[0]), "=r"(r[1]), "=r"(r[2]), "=r"(r[3]) : "r"(addr));
}
__device__ __forceinline__ void mma16816(float* d, const uint32_t* a,
                                         const uint32_t* b) {
    asm volatile("mma.sync.aligned.m16n8k16.row.col.f32.f16.f16.f32 "
        "{%0,%1,%2,%3}, {%4,%5,%6,%7}, {%8,%9}, {%0,%1,%2,%3};"
        : "+f"(d[0]), "+f"(d[1]), "+f"(d[2]), "+f"(d[3])
        : "r"(a[0]), "r"(a[1]), "r"(a[2]), "r"(a[3]), "r"(b[0]), "r"(b[1]));
}
__device__ __forceinline__ void cpasync16(uint32_t dst, const void* src) {
    asm volatile("cp.async.cg.shared.global [%0], [%1], 16;" :: "r"(dst), "l"(src));
}
#define CP_COMMIT()  asm volatile("cp.async.commit_group;" ::: "memory")
#define CP_WAIT(n)   asm volatile("cp.async.wait_group %0;" :: "n"(n) : "memory")

// pack two fp32 -> one f16x2 register (lo in low half)
__device__ __forceinline__ uint32_t f2h2(float lo, float hi) {
    uint32_t r;
    asm("cvt.rn.f16x2.f32 %0, %1, %2;" : "=r"(r) : "f"(hi), "f"(lo));
    return r;
}

// "a better than b" with first-index tie-break
__device__ __forceinline__ bool better(float av, int ai, float bv, int bi) {
    return (av > bv) || (av == bv && ai < bi);
}
// insert (v,k) into sorted top-3 (with tie-break)
__device__ __forceinline__ void ins3(float& v1, int& i1, float& v2, int& i2,
                                     float& v3, int& i3, float v, int k) {
    if (better(v, k, v1, i1))      { v3 = v2; i3 = i2; v2 = v1; i2 = i1; v1 = v; i1 = k; }
    else if (better(v, k, v2, i2)) { v3 = v2; i3 = i2; v2 = v; i2 = k; }
    else if (better(v, k, v3, i3)) { v3 = v; i3 = k; }
}

// pack 8 fp32 -> 4 f16x2
__device__ __forceinline__ uint4 pack8h(float4 v0, float4 v1) {
    uint4 o;
    o.x = f2h2(v0.x, v0.y);
    o.y = f2h2(v0.z, v0.w);
    o.z = f2h2(v1.x, v1.y);
    o.w = f2h2(v1.z, v1.w);
    return o;
}

// ---------------------------------------------------------------------------
// Kernel 1: normalize codebook rows; fp32 copy + fp16 pre-swizzled copy.
// ---------------------------------------------------------------------------
__global__ __launch_bounds__(256) void vq_prep_kernel(const float* __restrict__ w) {
    const int tid  = threadIdx.x;
    const int lane = tid & 31;
    const int row  = blockIdx.x * 8 + (tid >> 5);

    if (blockIdx.x < 4) g_counts[blockIdx.x * 256 + tid] = 0;

    const float4* W = (const float4*)(w + (long long)row * D_DIM);
    float4 a = W[lane * 2];
    float4 b = W[lane * 2 + 1];
    float s = a.x * a.x + a.y * a.y + a.z * a.z + a.w * a.w +
              b.x * b.x + b.y * b.y + b.z * b.z + b.w * b.w;
#pragma unroll
    for (int off = 16; off > 0; off >>= 1)
        s += __shfl_xor_sync(0xffffffffu, s, off);
    float inv = 1.0f / fmaxf(sqrtf(s), 1e-12f);

    a.x *= inv; a.y *= inv; a.z *= inv; a.w *= inv;
    b.x *= inv; b.y *= inv; b.z *= inv; b.w *= inv;

    float4* CF = (float4*)(g_cnormf + (long long)row * D_DIM);
    CF[lane * 2]     = a;
    CF[lane * 2 + 1] = b;

    const uint4 hp = pack8h(a, b);
    const int kc  = lane >> 3;                              // kc64 sub-chunk 0..3
    const int swb = (((lane & 7) * 16) ^ ((row & 7) << 4)); // swizzled byte col
    const int cb  = row >> 7;                               // code block 0..7
    const int cr  = row & 127;                              // row within block
    const long long base = ((long long)(cb * 4 + kc)) * 8192 + cr * 64 + (swb >> 1);
    *(uint4*)&g_cb[base] = hp;
}

// ---------------------------------------------------------------------------
// Kernel 2: single-product fp16 HMMA top-3. CTA = 128 tokens x 1024 codes.
// 1024 threads / 32 warps (8M x 4N), warp tile 16x32 -> 8 warps per SMSP.
// K-chunks of 128 (32KB B), double-buffered cp.async, one barrier per chunk.
// ---------------------------------------------------------------------------
#define A_OFF    0
#define B_OFF    65536
#define B_STRIDE 32768
#define SMEM_SZ  (65536 + 2 * 32768)
#define NTHR     1024

__global__ __launch_bounds__(NTHR, 1) void vq_argmax_mma_kernel(
    const float* __restrict__ z)
{
    extern __shared__ char smem[];
    const uint32_t sb  = smem_to_u32(smem);
    const int tid  = threadIdx.x;
    const int wid  = tid >> 5;   // 0..31
    const int l    = tid & 31;
    const int wm   = wid >> 2;   // 0..7 : rows [wm*16, +16)
    const int wn   = wid & 3;    // 0..3 : cols [wn*32, +32) within tile

    // prefetch B chunk 0 (32KB) while filling A
    {
        const uint32_t dst = sb + B_OFF;
#pragma unroll
        for (int i = 0; i < 2; i++)
            cpasync16(dst + tid * 16 + i * 16384, (const char*)g_cb + tid * 16 + i * 16384);
        CP_COMMIT();
    }

    // ---- A fill: 128 tokens x 256 fp16, SW128 swizzled, 4 kc64 sub-chunks ----
    {
        const long long zbase = (long long)blockIdx.x * 128 * D_DIM;
#pragma unroll 1
        for (int r = wid; r < 128; r += 32) {
            const float4* Z = (const float4*)(z + zbase + (long long)r * D_DIM);
            const uint4 hp = pack8h(Z[2 * l], Z[2 * l + 1]);
            const int kc  = l >> 3;
            const int swb = (((l & 7) * 16) ^ ((r & 7) << 4));
            *(uint4*)(smem + A_OFF + kc * 16384 + r * 128 + swb) = hp;
        }
    }

    // ldmatrix per-lane address constants (warp tile 16 rows x 32 cols)
    const int arow = l & 15;
    const int akb  = (l & 16) ? 16 : 0;
    const int rowA = wm * 16 + arow;
    const int aso  = rowA * 128;
    const int axr  = (rowA & 7) << 4;

    const int nB  = (l & 7) + ((l & 16) ? 8 : 0);
    const int bkb = (l & 8) ? 16 : 0;
    int bso[2], bxr[2];
#pragma unroll
    for (int np = 0; np < 2; np++) {
        const int nrow = wn * 32 + np * 16 + nB;
        bso[np] = nrow * 128;
        bxr[np] = (nrow & 7) << 4;
    }

    // top-3 state: 2 row-slots per thread (row l>>2 and row (l>>2)+8)
    float v1[2], v2[2], v3[2];
    int   i1[2], i2[2], i3[2];
#pragma unroll
    for (int s = 0; s < 2; s++) {
        v1[s] = v2[s] = v3[s] = -3.402823466e38f;
        i1[s] = i2[s] = i3[s] = 0;
    }

#pragma unroll 1
    for (int nt = 0; nt < 8; nt++) {              // code tiles of 128
        float d[4][4];                            // [n8 group][quad]
#pragma unroll
        for (int g = 0; g < 4; g++)
#pragma unroll
            for (int q = 0; q < 4; q++) d[g][q] = 0.f;

#pragma unroll 1
        for (int kc2 = 0; kc2 < 2; kc2++) {       // K chunks of 128
            const int c   = nt * 2 + kc2;
            const int buf = c & 1;

            CP_WAIT(0);        // own copies of chunk c landed
            __syncthreads();   // everyone's copies landed; prior buf readers done

            if (c < 15) {      // prefetch next 32KB chunk into the other buffer
                const int cn = c + 1;
                const char* src = (const char*)g_cb +
                    ((long long)((cn >> 1) * 4 + (cn & 1) * 2)) * 16384;
                const uint32_t dst = sb + B_OFF + (buf ^ 1) * B_STRIDE;
#pragma unroll
                for (int i = 0; i < 2; i++)
                    cpasync16(dst + tid * 16 + i * 16384, src + tid * 16 + i * 16384);
                CP_COMMIT();
            }

            const uint32_t bBase = sb + B_OFF + buf * B_STRIDE;
#pragma unroll
            for (int ks = 0; ks < 8; ks++) {      // k16 steps within 128
                const int sub = ks >> 2;          // kc64 sub-chunk within 128
                const int ksi = ks & 3;
                const uint32_t aBase = sb + A_OFF + (kc2 * 2 + sub) * 16384;
                uint32_t ah[4];
                ldm4(ah, aBase + aso + ((ksi * 32 + akb) ^ axr));
#pragma unroll
                for (int np = 0; np < 2; np++) {
                    uint32_t bh[4];
                    ldm4(bh, bBase + sub * 16384 + bso[np] +
                             ((ksi * 32 + bkb) ^ bxr[np]));
                    mma16816(d[np * 2],     ah, bh);
                    mma16816(d[np * 2 + 1], ah, bh + 2);
                }
            }
        }

        // fold 128 codes of this tile into running top-3 (ascending code order)
#pragma unroll
        for (int h = 0; h < 2; h++)               // row half: +0 / +8
#pragma unroll
            for (int g = 0; g < 4; g++)
#pragma unroll
                for (int j = 0; j < 2; j++) {
                    const float v = d[g][h * 2 + j];
                    const int   k = nt * 128 + wn * 32 + g * 8 + 2 * (l & 3) + j;
                    ins3(v1[h], i1[h], v2[h], i2[h], v3[h], i3[h], v, k);
                }
    }

    __syncthreads();   // compute done; reuse smem B region for reduction
    float* sv1 = (float*)(smem + B_OFF);            // [128][4]
    float* sv2 = (float*)(smem + B_OFF + 2048);
    float* sv3 = (float*)(smem + B_OFF + 4096);
    int*   si1 = (int*)(smem + B_OFF + 6144);
    int*   si2 = (int*)(smem + B_OFF + 8192);
    int*   si3 = (int*)(smem + B_OFF + 10240);

#pragma unroll
    for (int h = 0; h < 2; h++) {
        float a1 = v1[h], a2 = v2[h], a3 = v3[h];
        int   b1 = i1[h], b2 = i2[h], b3 = i3[h];
#pragma unroll
        for (int off = 1; off <= 2; off <<= 1) {
            const float w1 = __shfl_xor_sync(0xffffffffu, a1, off);
            const int   j1 = __shfl_xor_sync(0xffffffffu, b1, off);
            const float w2 = __shfl_xor_sync(0xffffffffu, a2, off);
            const int   j2 = __shfl_xor_sync(0xffffffffu, b2, off);
            const float w3 = __shfl_xor_sync(0xffffffffu, a3, off);
            const int   j3 = __shfl_xor_sync(0xffffffffu, b3, off);
            ins3(a1, b1, a2, b2, a3, b3, w1, j1);
            ins3(a1, b1, a2, b2, a3, b3, w2, j2);
            ins3(a1, b1, a2, b2, a3, b3, w3, j3);
        }
        if ((l & 3) == 0) {
            const int row = wm * 16 + (l >> 2) + 8 * h;
            sv1[row * 4 + wn] = a1; si1[row * 4 + wn] = b1;
            sv2[row * 4 + wn] = a2; si2[row * 4 + wn] = b2;
            sv3[row * 4 + wn] = a3; si3[row * 4 + wn] = b3;
        }
    }
    __syncthreads();

    if (tid < 128) {
        float a1 = sv1[tid * 4], a2 = sv2[tid * 4], a3 = sv3[tid * 4];
        int   b1 = si1[tid * 4], b2 = si2[tid * 4], b3 = si3[tid * 4];
#pragma unroll
        for (int e = 1; e < 4; e++) {
            ins3(a1, b1, a2, b2, a3, b3, sv1[tid * 4 + e], si1[tid * 4 + e]);
            ins3(a1, b1, a2, b2, a3, b3, sv2[tid * 4 + e], si2[tid * 4 + e]);
            ins3(a1, b1, a2, b2, a3, b3, sv3[tid * 4 + e], si3[tid * 4 + e]);
        }
        const float gap = a1 - a2;
        g_top3[blockIdx.x * 128 + tid] = make_int4(b1, b2, b3, __float_as_int(gap));
    }
}

// ---------------------------------------------------------------------------
// Kernel 3: conditional fp32 rescore (only if noisy gap small), gather z_q,
// loss partial, histogram, index output.
// ---------------------------------------------------------------------------
__global__ __launch_bounds__(256) void vq_gather_kernel(
    const float* __restrict__ z, const float* __restrict__ w,
    float* __restrict__ zq, float* __restrict__ out_idx_f, int write_idx)
{
    const int tid  = threadIdx.x;
    const int warp = tid >> 5;
    const int lane = tid & 31;
    const int tok0 = blockIdx.x * 128 + warp * 16;

    float acc = 0.f;
#pragma unroll 1
    for (int t = 0; t < 16; t++) {
        const int tok = tok0 + t;
        const int4 c = g_top3[tok];
        const float4* Z = (const float4*)(z + (long long)tok * D_DIM);
        const float4 za = Z[lane * 2], zb = Z[lane * 2 + 1];

        int k = c.x;
        if (__int_as_float(c.w) <= GAP_THRESH) {
            // exact fp32 rescore of the 3 candidates
            float dd[3];
            const int cand[3] = {c.x, c.y, c.z};
#pragma unroll
            for (int e = 0; e < 3; e++) {
                const float4* C = (const float4*)(g_cnormf + (long long)cand[e] * D_DIM);
                const float4 p = C[lane * 2], q = C[lane * 2 + 1];
                dd[e] = za.x * p.x + za.y * p.y + za.z * p.z + za.w * p.w +
                        zb.x * q.x + zb.y * q.y + zb.z * q.z + zb.w * q.w;
            }
#pragma unroll
            for (int off = 16; off > 0; off >>= 1) {
                dd[0] += __shfl_xor_sync(0xffffffffu, dd[0], off);
                dd[1] += __shfl_xor_sync(0xffffffffu, dd[1], off);
                dd[2] += __shfl_xor_sync(0xffffffffu, dd[2], off);
            }
            float bvv = dd[0]; int bii = c.x;
            if (better(dd[1], c.y, bvv, bii)) { bvv = dd[1]; bii = c.y; }
            if (better(dd[2], c.z, bvv, bii)) { bvv = dd[2]; bii = c.z; }
            k = bii;
        }

        const float4* W = (const float4*)(w + (long long)k * D_DIM);
        float4*       Q = (float4*)(zq + (long long)tok * D_DIM);
        const float4 a = W[lane * 2], b = W[lane * 2 + 1];
        Q[lane * 2]     = a;
        Q[lane * 2 + 1] = b;
        float dx;
        dx = a.x - za.x; acc += dx * dx;
        dx = a.y - za.y; acc += dx * dx;
        dx = a.z - za.z; acc += dx * dx;
        dx = a.w - za.w; acc += dx * dx;
        dx = b.x - zb.x; acc += dx * dx;
        dx = b.y - zb.y; acc += dx * dx;
        dx = b.z - zb.z; acc += dx * dx;
        dx = b.w - zb.w; acc += dx * dx;

        if (lane == 0) {
            atomicAdd(&g_counts[k], 1);
            if (write_idx) out_idx_f[tok] = (float)k;
        }
    }
#pragma unroll
    for (int off = 16; off > 0; off >>= 1)
        acc += __shfl_xor_sync(0xffffffffu, acc, off);

    __shared__ float sh[8];
    if (lane == 0) sh[warp] = acc;
    __syncthreads();
    if (tid == 0) {
        float s = 0.f;
#pragma unroll
        for (int i = 0; i < 8; i++) s += sh[i];
        g_partials[blockIdx.x] = (double)s;
    }
}

// ---------------------------------------------------------------------------
// Kernel 4: finalize loss + perplexity.
// ---------------------------------------------------------------------------
__global__ __launch_bounds__(256) void vq_finalize_kernel(
    float* __restrict__ out, long long Nz, int N, int nPart)
{
    __shared__ double sh[256];
    const int tid = threadIdx.x;

    double s = 0.0;
    for (int i = tid; i < nPart; i += 256) s += g_partials[i];
    sh[tid] = s;
    __syncthreads();
    for (int st = 128; st > 0; st >>= 1) {
        if (tid < st) sh[tid] += sh[tid + st];
        __syncthreads();
    }
    const double total = sh[0];
    __syncthreads();

    float e = 0.f;
    for (int b = tid; b < K_CODES; b += 256) {
        float p = (float)g_counts[b] / (float)N;
        e += p * logf(p + 1e-10f);
    }
    sh[tid] = (double)e;
    __syncthreads();
    for (int st = 128; st > 0; st >>= 1) {
        if (tid < st) sh[tid] += sh[tid + st];
        __syncthreads();
    }
    if (tid == 0) {
        out[Nz]     = (float)(1.25 * total / ((double)N * (double)D_DIM));
        out[Nz + 1] = expf(-(float)sh[0]);
    }
}

// ---------------------------------------------------------------------------
extern "C" void kernel_launch(void* const* d_in, const int* in_sizes, int n_in,
                              void* d_out, int out_size)
{
    const float* z = (const float*)d_in[0];
    const float* w = (const float*)d_in[1];
    float* out = (float*)d_out;

    const int Nz = in_sizes[0];      // 33554432
    const int N  = Nz / D_DIM;       // 131072 tokens
    const int nBlk = N / 128;        // 1024

    const int write_idx = (out_size >= Nz + 2 + N) ? 1 : 0;

    cudaFuncSetAttribute(vq_argmax_mma_kernel,
                         cudaFuncAttributeMaxDynamicSharedMemorySize, SMEM_SZ);

    vq_prep_kernel<<<K_CODES / 8, 256>>>(w);
    vq_argmax_mma_kernel<<<nBlk, NTHR, SMEM_SZ>>>(z);
    vq_gather_kernel<<<nBlk, 256>>>(z, w, out, out + (size_t)Nz + 2, write_idx);
    vq_finalize_kernel<<<1, 256>>>(out, (long long)Nz, N, nBlk);
}

// round 14
// speedup vs baseline: 3.6142x; 1.1565x over previous
#include <cuda_runtime.h>
#include <cuda_fp16.h>
#include <stdint.h>
#include <math.h>

// Problem constants (z: [32,4096,256] fp32, embed: [1024,256] fp32)
#define D_DIM   256
#define K_CODES 1024
#define MAX_N   131072

// ---------------------------------------------------------------------------
// Device globals (no cudaMalloc allowed)
// ---------------------------------------------------------------------------
// g_cb layout: [code_block(8)][kc64(4)][128 codes x 64 elems, SW128 swizzled]
// so one (nt, kchunk128) B chunk = 2 consecutive kc64 blocks = contiguous 32KB.
__device__ __half  g_cb[K_CODES * D_DIM];
__device__ float   g_cnormf[K_CODES * D_DIM];  // normalized codebook fp32 (rescore)
__device__ int4    g_top3[MAX_N];              // (i1, i2, i3, gap_as_float_bits)
__device__ int     g_counts[K_CODES];
__device__ double  g_partials[MAX_N / 128];

#define GAP_THRESH 8e-3f

// ---------------------------------------------------------------------------
// PTX helpers (base sm_103 target)
// ---------------------------------------------------------------------------
__device__ __forceinline__ uint32_t smem_to_u32(const void* p) {
    uint32_t a;
    asm("{ .reg .u64 t; cvta.to.shared.u64 t, %1; cvt.u32.u64 %0, t; }" : "=r"(a) : "l"(p));
    return a;
}
__device__ __forceinline__ void ldm4(uint32_t* r, uint32_t addr) {
    asm volatile("ldmatrix.sync.aligned.m8n8.x4.shared.b16 {%0,%1,%2,%3}, [%4];"
        : "=r"(r[0]), "=r"(r[1]), "=r"(r[2]), "=r"(r[3]) : "r"(addr));
}
__device__ __forceinline__ void mma16816(float* d, const uint32_t* a,
                                         const uint32_t* b) {
    asm volatile("mma.sync.aligned.m16n8k16.row.col.f32.f16.f16.f32 "
        "{%0,%1,%2,%3}, {%4,%5,%6,%7}, {%8,%9}, {%0,%1,%2,%3};"
        : "+f"(d[0]), "+f"(d[1]), "+f"(d[2]), "+f"(d[3])
        : "r"(a[0]), "r"(a[1]), "r"(a[2]), "r"(a[3]), "r"(b[0]), "r"(b[1]));
}
__device__ __forceinline__ void cpasync16(uint32_t dst, const void* src) {
    asm volatile("cp.async.cg.shared.global [%0], [%1], 16;" :: "r"(dst), "l"(src));
}
#define CP_COMMIT()  asm volatile("cp.async.commit_group;" ::: "memory")
#define CP_WAIT(n)   asm volatile("cp.async.wait_group %0;" :: "n"(n) : "memory")

// pack two fp32 -> one f16x2 register (lo in low half)
__device__ __forceinline__ uint32_t f2h2(float lo, float hi) {
    uint32_t r;
    asm("cvt.rn.f16x2.f32 %0, %1, %2;" : "=r"(r) : "f"(hi), "f"(lo));
    return r;
}

// "a better than b" with first-index tie-break
__device__ __forceinline__ bool better(float av, int ai, float bv, int bi) {
    return (av > bv) || (av == bv && ai < bi);
}
// insert (v,k) into sorted top-3 (with tie-break)
__device__ __forceinline__ void ins3(float& v1, int& i1, float& v2, int& i2,
                                     float& v3, int& i3, float v, int k) {
    if (better(v, k, v1, i1))      { v3 = v2; i3 = i2; v2 = v1; i2 = i1; v1 = v; i1 = k; }
    else if (better(v, k, v2, i2)) { v3 = v2; i3 = i2; v2 = v; i2 = k; }
    else if (better(v, k, v3, i3)) { v3 = v; i3 = k; }
}

// pack 8 fp32 -> 4 f16x2
__device__ __forceinline__ uint4 pack8h(float4 v0, float4 v1) {
    uint4 o;
    o.x = f2h2(v0.x, v0.y);
    o.y = f2h2(v0.z, v0.w);
    o.z = f2h2(v1.x, v1.y);
    o.w = f2h2(v1.z, v1.w);
    return o;
}

// ---------------------------------------------------------------------------
// Kernel 1: normalize codebook rows; fp32 copy + fp16 pre-swizzled copy.
// ---------------------------------------------------------------------------
__global__ __launch_bounds__(256) void vq_prep_kernel(const float* __restrict__ w) {
    const int tid  = threadIdx.x;
    const int lane = tid & 31;
    const int row  = blockIdx.x * 8 + (tid >> 5);

    if (blockIdx.x < 4) g_counts[blockIdx.x * 256 + tid] = 0;

    const float4* W = (const float4*)(w + (long long)row * D_DIM);
    float4 a = W[lane * 2];
    float4 b = W[lane * 2 + 1];
    float s = a.x * a.x + a.y * a.y + a.z * a.z + a.w * a.w +
              b.x * b.x + b.y * b.y + b.z * b.z + b.w * b.w;
#pragma unroll
    for (int off = 16; off > 0; off >>= 1)
        s += __shfl_xor_sync(0xffffffffu, s, off);
    float inv = 1.0f / fmaxf(sqrtf(s), 1e-12f);

    a.x *= inv; a.y *= inv; a.z *= inv; a.w *= inv;
    b.x *= inv; b.y *= inv; b.z *= inv; b.w *= inv;

    float4* CF = (float4*)(g_cnormf + (long long)row * D_DIM);
    CF[lane * 2]     = a;
    CF[lane * 2 + 1] = b;

    const uint4 hp = pack8h(a, b);
    const int kc  = lane >> 3;                              // kc64 sub-chunk 0..3
    const int swb = (((lane & 7) * 16) ^ ((row & 7) << 4)); // swizzled byte col
    const int cb  = row >> 7;                               // code block 0..7
    const int cr  = row & 127;                              // row within block
    const long long base = ((long long)(cb * 4 + kc)) * 8192 + cr * 64 + (swb >> 1);
    *(uint4*)&g_cb[base] = hp;
}

// ---------------------------------------------------------------------------
// Kernel 2: single-product fp16 HMMA top-3. CTA = 64 tokens x 1024 codes.
// 512 threads / 16 warps (4M x 4N), warp tile 16x32, occupancy 2 -> two
// independent barrier domains per SM overlap each other's convoys.
// K-chunks of 128 (32KB B), double-buffered cp.async, one barrier per chunk.
// ---------------------------------------------------------------------------
#define A_OFF    0
#define B_OFF    32768
#define B_STRIDE 32768
#define SMEM_SZ  (32768 + 2 * 32768)   // 96KB -> 2 CTAs/SM
#define NTHR     512

__global__ __launch_bounds__(NTHR, 2) void vq_argmax_mma_kernel(
    const float* __restrict__ z)
{
    extern __shared__ char smem[];
    const uint32_t sb  = smem_to_u32(smem);
    const int tid  = threadIdx.x;
    const int wid  = tid >> 5;   // 0..15
    const int l    = tid & 31;
    const int wm   = wid >> 2;   // 0..3 : rows [wm*16, +16)
    const int wn   = wid & 3;    // 0..3 : cols [wn*32, +32) within tile

    // prefetch B chunk 0 (32KB) while filling A
    {
        const uint32_t dst = sb + B_OFF;
#pragma unroll
        for (int i = 0; i < 4; i++)
            cpasync16(dst + tid * 16 + i * 8192, (const char*)g_cb + tid * 16 + i * 8192);
        CP_COMMIT();
    }

    // ---- A fill: 64 tokens x 256 fp16, SW128 swizzled, 4 kc64 sub-chunks ----
    {
        const long long zbase = (long long)blockIdx.x * 64 * D_DIM;
#pragma unroll 1
        for (int r = wid; r < 64; r += 16) {
            const float4* Z = (const float4*)(z + zbase + (long long)r * D_DIM);
            const uint4 hp = pack8h(Z[2 * l], Z[2 * l + 1]);
            const int kc  = l >> 3;
            const int swb = (((l & 7) * 16) ^ ((r & 7) << 4));
            *(uint4*)(smem + A_OFF + kc * 8192 + r * 128 + swb) = hp;
        }
    }

    // ldmatrix per-lane address constants (warp tile 16 rows x 32 cols)
    const int arow = l & 15;
    const int akb  = (l & 16) ? 16 : 0;
    const int rowA = wm * 16 + arow;
    const int aso  = rowA * 128;
    const int axr  = (rowA & 7) << 4;

    const int nB  = (l & 7) + ((l & 16) ? 8 : 0);
    const int bkb = (l & 8) ? 16 : 0;
    int bso[2], bxr[2];
#pragma unroll
    for (int np = 0; np < 2; np++) {
        const int nrow = wn * 32 + np * 16 + nB;
        bso[np] = nrow * 128;
        bxr[np] = (nrow & 7) << 4;
    }

    // top-3 state: 2 row-slots per thread (row l>>2 and row (l>>2)+8)
    float v1[2], v2[2], v3[2];
    int   i1[2], i2[2], i3[2];
#pragma unroll
    for (int s = 0; s < 2; s++) {
        v1[s] = v2[s] = v3[s] = -3.402823466e38f;
        i1[s] = i2[s] = i3[s] = 0;
    }

#pragma unroll 1
    for (int nt = 0; nt < 8; nt++) {              // code tiles of 128
        float d[4][4];                            // [n8 group][quad]
#pragma unroll
        for (int g = 0; g < 4; g++)
#pragma unroll
            for (int q = 0; q < 4; q++) d[g][q] = 0.f;

#pragma unroll 1
        for (int kc2 = 0; kc2 < 2; kc2++) {       // K chunks of 128
            const int c   = nt * 2 + kc2;
            const int buf = c & 1;

            CP_WAIT(0);        // own copies of chunk c landed
            __syncthreads();   // everyone's copies landed; prior buf readers done

            if (c < 15) {      // prefetch next 32KB chunk into the other buffer
                const int cn = c + 1;
                const char* src = (const char*)g_cb +
                    ((long long)((cn >> 1) * 4 + (cn & 1) * 2)) * 16384;
                const uint32_t dst = sb + B_OFF + (buf ^ 1) * B_STRIDE;
#pragma unroll
                for (int i = 0; i < 4; i++)
                    cpasync16(dst + tid * 16 + i * 8192, src + tid * 16 + i * 8192);
                CP_COMMIT();
            }

            const uint32_t bBase = sb + B_OFF + buf * B_STRIDE;
#pragma unroll
            for (int ks = 0; ks < 8; ks++) {      // k16 steps within 128
                const int sub = ks >> 2;          // kc64 sub-chunk within 128
                const int ksi = ks & 3;
                const uint32_t aBase = sb + A_OFF + (kc2 * 2 + sub) * 8192;
                uint32_t ah[4];
                ldm4(ah, aBase + aso + ((ksi * 32 + akb) ^ axr));
#pragma unroll
                for (int np = 0; np < 2; np++) {
                    uint32_t bh[4];
                    ldm4(bh, bBase + sub * 16384 + bso[np] +
                             ((ksi * 32 + bkb) ^ bxr[np]));
                    mma16816(d[np * 2],     ah, bh);
                    mma16816(d[np * 2 + 1], ah, bh + 2);
                }
            }
        }

        // fold 128 codes of this tile into running top-3 (ascending code order)
#pragma unroll
        for (int h = 0; h < 2; h++)               // row half: +0 / +8
#pragma unroll
            for (int g = 0; g < 4; g++)
#pragma unroll
                for (int j = 0; j < 2; j++) {
                    const float v = d[g][h * 2 + j];
                    const int   k = nt * 128 + wn * 32 + g * 8 + 2 * (l & 3) + j;
                    ins3(v1[h], i1[h], v2[h], i2[h], v3[h], i3[h], v, k);
                }
    }

    __syncthreads();   // compute done; reuse smem B region for reduction
    float* sv1 = (float*)(smem + B_OFF);            // [64][4]
    float* sv2 = (float*)(smem + B_OFF + 1024);
    float* sv3 = (float*)(smem + B_OFF + 2048);
    int*   si1 = (int*)(smem + B_OFF + 3072);
    int*   si2 = (int*)(smem + B_OFF + 4096);
    int*   si3 = (int*)(smem + B_OFF + 5120);

#pragma unroll
    for (int h = 0; h < 2; h++) {
        float a1 = v1[h], a2 = v2[h], a3 = v3[h];
        int   b1 = i1[h], b2 = i2[h], b3 = i3[h];
#pragma unroll
        for (int off = 1; off <= 2; off <<= 1) {
            const float w1 = __shfl_xor_sync(0xffffffffu, a1, off);
            const int   j1 = __shfl_xor_sync(0xffffffffu, b1, off);
            const float w2 = __shfl_xor_sync(0xffffffffu, a2, off);
            const int   j2 = __shfl_xor_sync(0xffffffffu, b2, off);
            const float w3 = __shfl_xor_sync(0xffffffffu, a3, off);
            const int   j3 = __shfl_xor_sync(0xffffffffu, b3, off);
            ins3(a1, b1, a2, b2, a3, b3, w1, j1);
            ins3(a1, b1, a2, b2, a3, b3, w2, j2);
            ins3(a1, b1, a2, b2, a3, b3, w3, j3);
        }
        if ((l & 3) == 0) {
            const int row = wm * 16 + (l >> 2) + 8 * h;
            sv1[row * 4 + wn] = a1; si1[row * 4 + wn] = b1;
            sv2[row * 4 + wn] = a2; si2[row * 4 + wn] = b2;
            sv3[row * 4 + wn] = a3; si3[row * 4 + wn] = b3;
        }
    }
    __syncthreads();

    if (tid < 64) {
        float a1 = sv1[tid * 4], a2 = sv2[tid * 4], a3 = sv3[tid * 4];
        int   b1 = si1[tid * 4], b2 = si2[tid * 4], b3 = si3[tid * 4];
#pragma unroll
        for (int e = 1; e < 4; e++) {
            ins3(a1, b1, a2, b2, a3, b3, sv1[tid * 4 + e], si1[tid * 4 + e]);
            ins3(a1, b1, a2, b2, a3, b3, sv2[tid * 4 + e], si2[tid * 4 + e]);
            ins3(a1, b1, a2, b2, a3, b3, sv3[tid * 4 + e], si3[tid * 4 + e]);
        }
        const float gap = a1 - a2;
        g_top3[blockIdx.x * 64 + tid] = make_int4(b1, b2, b3, __float_as_int(gap));
    }
}

// ---------------------------------------------------------------------------
// Kernel 3: conditional fp32 rescore (only if noisy gap small), gather z_q,
// loss partial, histogram, index output.
// ---------------------------------------------------------------------------
__global__ __launch_bounds__(256) void vq_gather_kernel(
    const float* __restrict__ z, const float* __restrict__ w,
    float* __restrict__ zq, float* __restrict__ out_idx_f, int write_idx)
{
    const int tid  = threadIdx.x;
    const int warp = tid >> 5;
    const int lane = tid & 31;
    const int tok0 = blockIdx.x * 128 + warp * 16;

    float acc = 0.f;
#pragma unroll 1
    for (int t = 0; t < 16; t++) {
        const int tok = tok0 + t;
        const int4 c = g_top3[tok];
        const float4* Z = (const float4*)(z + (long long)tok * D_DIM);
        const float4 za = Z[lane * 2], zb = Z[lane * 2 + 1];

        int k = c.x;
        if (__int_as_float(c.w) <= GAP_THRESH) {
            // exact fp32 rescore of the 3 candidates
            float dd[3];
            const int cand[3] = {c.x, c.y, c.z};
#pragma unroll
            for (int e = 0; e < 3; e++) {
                const float4* C = (const float4*)(g_cnormf + (long long)cand[e] * D_DIM);
                const float4 p = C[lane * 2], q = C[lane * 2 + 1];
                dd[e] = za.x * p.x + za.y * p.y + za.z * p.z + za.w * p.w +
                        zb.x * q.x + zb.y * q.y + zb.z * q.z + zb.w * q.w;
            }
#pragma unroll
            for (int off = 16; off > 0; off >>= 1) {
                dd[0] += __shfl_xor_sync(0xffffffffu, dd[0], off);
                dd[1] += __shfl_xor_sync(0xffffffffu, dd[1], off);
                dd[2] += __shfl_xor_sync(0xffffffffu, dd[2], off);
            }
            float bvv = dd[0]; int bii = c.x;
            if (better(dd[1], c.y, bvv, bii)) { bvv = dd[1]; bii = c.y; }
            if (better(dd[2], c.z, bvv, bii)) { bvv = dd[2]; bii = c.z; }
            k = bii;
        }

        const float4* W = (const float4*)(w + (long long)k * D_DIM);
        float4*       Q = (float4*)(zq + (long long)tok * D_DIM);
        const float4 a = W[lane * 2], b = W[lane * 2 + 1];
        Q[lane * 2]     = a;
        Q[lane * 2 + 1] = b;
        float dx;
        dx = a.x - za.x; acc += dx * dx;
        dx = a.y - za.y; acc += dx * dx;
        dx = a.z - za.z; acc += dx * dx;
        dx = a.w - za.w; acc += dx * dx;
        dx = b.x - zb.x; acc += dx * dx;
        dx = b.y - zb.y; acc += dx * dx;
        dx = b.z - zb.z; acc += dx * dx;
        dx = b.w - zb.w; acc += dx * dx;

        if (lane == 0) {
            atomicAdd(&g_counts[k], 1);
            if (write_idx) out_idx_f[tok] = (float)k;
        }
    }
#pragma unroll
    for (int off = 16; off > 0; off >>= 1)
        acc += __shfl_xor_sync(0xffffffffu, acc, off);

    __shared__ float sh[8];
    if (lane == 0) sh[warp] = acc;
    __syncthreads();
    if (tid == 0) {
        float s = 0.f;
#pragma unroll
        for (int i = 0; i < 8; i++) s += sh[i];
        g_partials[blockIdx.x] = (double)s;
    }
}

// ---------------------------------------------------------------------------
// Kernel 4: finalize loss + perplexity.
// ---------------------------------------------------------------------------
__global__ __launch_bounds__(256) void vq_finalize_kernel(
    float* __restrict__ out, long long Nz, int N, int nPart)
{
    __shared__ double sh[256];
    const int tid = threadIdx.x;

    double s = 0.0;
    for (int i = tid; i < nPart; i += 256) s += g_partials[i];
    sh[tid] = s;
    __syncthreads();
    for (int st = 128; st > 0; st >>= 1) {
        if (tid < st) sh[tid] += sh[tid + st];
        __syncthreads();
    }
    const double total = sh[0];
    __syncthreads();

    float e = 0.f;
    for (int b = tid; b < K_CODES; b += 256) {
        float p = (float)g_counts[b] / (float)N;
        e += p * logf(p + 1e-10f);
    }
    sh[tid] = (double)e;
    __syncthreads();
    for (int st = 128; st > 0; st >>= 1) {
        if (tid < st) sh[tid] += sh[tid + st];
        __syncthreads();
    }
    if (tid == 0) {
        out[Nz]     = (float)(1.25 * total / ((double)N * (double)D_DIM));
        out[Nz + 1] = expf(-(float)sh[0]);
    }
}

// ---------------------------------------------------------------------------
extern "C" void kernel_launch(void* const* d_in, const int* in_sizes, int n_in,
                              void* d_out, int out_size)
{
    const float* z = (const float*)d_in[0];
    const float* w = (const float*)d_in[1];
    float* out = (float*)d_out;

    const int Nz = in_sizes[0];      // 33554432
    const int N  = Nz / D_DIM;       // 131072 tokens
    const int nBlk = N / 128;        // 1024 (gather)
    const int nBlkA = N / 64;        // 2048 (argmax, 64 tokens/CTA)

    const int write_idx = (out_size >= Nz + 2 + N) ? 1 : 0;

    cudaFuncSetAttribute(vq_argmax_mma_kernel,
                         cudaFuncAttributeMaxDynamicSharedMemorySize, SMEM_SZ);

    vq_prep_kernel<<<K_CODES / 8, 256>>>(w);
    vq_argmax_mma_kernel<<<nBlkA, NTHR, SMEM_SZ>>>(z);
    vq_gather_kernel<<<nBlk, 256>>>(z, w, out, out + (size_t)Nz + 2, write_idx);
    vq_finalize_kernel<<<1, 256>>>(out, (long long)Nz, N, nBlk);
}